// round 12
// baseline (speedup 1.0000x reference)
#include <cuda_runtime.h>
#include <cuda_bf16.h>
#include <mma.h>
#include <cstdint>
using namespace nvcuda;

#define HH 256
#define WW 256
#define BB 2
#define CC 64
#define EPSV 1e-5f
#define NPIX (HH*WW)
#define NGRP 16
#define NELEM_GRP (8*NPIX*2)

// ---------------- scratch ----------------
__device__ float g_t[2][BB][CC][HH][WW];
__device__ float g_s[2][BB][CC][HH][WW];
__device__ float g_sum_x[NGRP], g_ssq_x[NGRP];
__device__ float g_sum_t[NGRP], g_ssq_t[NGRP];
__device__ float g_sum_s[NGRP], g_ssq_s[NGRP];
__device__ float g_mean1[NGRP], g_inv1[NGRP];
__device__ float g_mean2[NGRP], g_inv2[NGRP];
__device__ float g_means[NGRP], g_invs[NGRP];

// ---------------- small kernels ----------------
__global__ void zero_stats_k() {
    int i = threadIdx.x;
    if (i < NGRP) {
        g_sum_x[i] = 0.f; g_ssq_x[i] = 0.f;
        g_sum_t[i] = 0.f; g_ssq_t[i] = 0.f;
        g_sum_s[i] = 0.f; g_ssq_s[i] = 0.f;
    }
}

__global__ void finalize1_k() {
    int i = threadIdx.x;
    if (i < NGRP) {
        float n = (float)NELEM_GRP;
        float m = g_sum_x[i] / n;
        float v = g_ssq_x[i] / n - m*m;
        g_mean1[i] = m; g_inv1[i] = rsqrtf(v + EPSV);
    }
}

__global__ void finalize2_k() {
    int i = threadIdx.x;
    float n = (float)NELEM_GRP;
    if (i < NGRP) {
        float m = g_sum_t[i] / n;
        float v = g_ssq_t[i] / n - m*m;
        g_mean2[i] = m; g_inv2[i] = rsqrtf(v + EPSV);
    } else if (i < 2*NGRP) {
        int j = i - NGRP;
        float m = g_sum_s[j] / n;
        float v = g_ssq_s[j] / n - m*m;
        g_means[j] = m; g_invs[j] = rsqrtf(v + EPSV);
    }
}

// ---------------- skip kernel (round-5 proven) ----------------
__global__ __launch_bounds__(256, 4)
void skip_k(const float* __restrict__ x0, const float* __restrict__ x1,
            const float* __restrict__ Ws, const float* __restrict__ Bs)
{
    __shared__ float sW[32*64];
    __shared__ float sX[2048];

    int tid = threadIdx.x, warp = tid >> 5, lane = tid & 31;
    int r = lane >> 2, cb = (lane & 3) * 4;
    int z = blockIdx.z; int b = z & 1, cs = (z >> 1) & 1, half = z >> 2;
    int oc0 = half * 32 + warp * 4;
    int y0 = blockIdx.y * 8, xb = blockIdx.x * 16;

    const float* xbase = (cs ? x1 : x0) + (size_t)b * CC * NPIX;

    for (int idx = tid; idx < 2048; idx += 256)
        sW[idx] = Ws[(size_t)(half*32 + (idx >> 6)) * 64 + (idx & 63)];

    float acc[4][4];
    #pragma unroll
    for (int o = 0; o < 4; ++o) {
        float bv = Bs[oc0 + o];
        #pragma unroll
        for (int p = 0; p < 4; ++p) acc[o][p] = bv;
    }

    for (int icc = 0; icc < 4; ++icc) {
        __syncthreads();
        for (int idx = tid; idx < 512; idx += 256) {
            int ic = idx >> 5, q = idx & 31;
            int row = q >> 2, c4 = (q & 3) * 4;
            const float* src = xbase + (size_t)(icc*16+ic)*NPIX
                               + (size_t)(y0+row)*WW + xb + c4;
            *(float4*)&sX[ic*128 + row*16 + c4] = *(const float4*)src;
        }
        __syncthreads();

        float xs0 = 0.f, xq0 = 0.f, xs1 = 0.f, xq1 = 0.f;
        bool do_stats = (half == 0) && (warp == 0);
        #pragma unroll 4
        for (int ic = 0; ic < 16; ++ic) {
            int gic = icc*16 + ic;
            float4 rv = *(float4*)&sX[ic*128 + r*16 + cb];
            if (do_stats) {
                float s = (rv.x + rv.y) + (rv.z + rv.w);
                float q = (rv.x*rv.x + rv.y*rv.y) + (rv.z*rv.z + rv.w*rv.w);
                if (ic < 8) { xs0 += s; xq0 += q; } else { xs1 += s; xq1 += q; }
            }
            #pragma unroll
            for (int o = 0; o < 4; ++o) {
                float w = sW[(warp*4 + o)*64 + gic];
                acc[o][0] = fmaf(w, rv.x, acc[o][0]);
                acc[o][1] = fmaf(w, rv.y, acc[o][1]);
                acc[o][2] = fmaf(w, rv.z, acc[o][2]);
                acc[o][3] = fmaf(w, rv.w, acc[o][3]);
            }
        }
        if (do_stats) {
            #pragma unroll
            for (int off = 16; off; off >>= 1) {
                xs0 += __shfl_xor_sync(0xffffffffu, xs0, off);
                xq0 += __shfl_xor_sync(0xffffffffu, xq0, off);
                xs1 += __shfl_xor_sync(0xffffffffu, xs1, off);
                xq1 += __shfl_xor_sync(0xffffffffu, xq1, off);
            }
            if (lane == 0) {
                atomicAdd(&g_sum_x[b*8 + icc*2],     xs0);
                atomicAdd(&g_ssq_x[b*8 + icc*2],     xq0);
                atomicAdd(&g_sum_x[b*8 + icc*2 + 1], xs1);
                atomicAdd(&g_ssq_x[b*8 + icc*2 + 1], xq1);
            }
        }
    }

    size_t pixoff = (size_t)(y0 + r) * WW + xb + cb;
    float sv = 0.f, ssv = 0.f;
    #pragma unroll
    for (int o = 0; o < 4; ++o) {
        float* sp = &g_s[cs][b][oc0 + o][0][0] + pixoff;
        *(float4*)sp = make_float4(acc[o][0], acc[o][1], acc[o][2], acc[o][3]);
        #pragma unroll
        for (int p = 0; p < 4; ++p) { sv += acc[o][p]; ssv += acc[o][p]*acc[o][p]; }
    }
    #pragma unroll
    for (int off = 16; off; off >>= 1) {
        sv  += __shfl_xor_sync(0xffffffffu, sv,  off);
        ssv += __shfl_xor_sync(0xffffffffu, ssv, off);
    }
    if (lane == 0) {
        int gi = b*8 + (oc0 >> 3);
        atomicAdd(&g_sum_s[gi], sv); atomicAdd(&g_ssq_s[gi], ssv);
    }
}

// ---------------- wmma conv kernel ----------------
// grid (2, 256, 4); 256 thr = 8 warps. Tiles: 4 octiles x 8 pxtiles; warp does 4.
// smem byte offsets (all 32B aligned; activation/weight rows = 64 bf16 = 128B):
#define W_MISC  0
#define W_W     1280                       // 10 mats * 64*128 = 81920
#define W_CEN_H 83200                      // 128 rows
#define W_CEN_L 99584
#define W_CRS_H 115968                     // 260 rows
#define W_CRS_L 149248
#define W_CST   182528                     // 8 warps * 16*20 floats
#define W_TOTAL 192768
#define CR_STRIDE 130

template<int PASS>
__global__ __launch_bounds__(256, 1)
void conv_w_k(const float* __restrict__ in0, const float* __restrict__ in1,
              const float* __restrict__ Wc, const float* __restrict__ Wk,
              const float* __restrict__ Bi,
              const float* __restrict__ Ga, const float* __restrict__ Be,
              const float* __restrict__ Gs, const float* __restrict__ BeS,
              float* __restrict__ Out)
{
    extern __shared__ __align__(128) char smraw[];
    float* sScale = (float*)(smraw + W_MISC);
    float* sShift = sScale + 64;
    float* sBias  = sShift + 64;
    float* sB2    = sBias + 64;
    float* sB3    = sB2 + 64;

    int tid = threadIdx.x, warp = tid >> 5, lane = tid & 31;
    int bc = blockIdx.z; int b = bc & 1, cs = bc >> 1;
    int y = blockIdx.y;
    int x0 = blockIdx.x * 128;

    const float* same_base;
    const float* cross_base;
    if (PASS == 1) {
        same_base  = (cs ? in1 : in0) + (size_t)b * CC * NPIX;
        cross_base = (cs ? in0 : in1) + (size_t)b * CC * NPIX;
    } else {
        same_base  = &g_t[cs][b][0][0][0];
        cross_base = &g_t[cs ^ 1][b][0][0][0];
    }
    const float* meanA = (PASS == 1) ? g_mean1 : g_mean2;
    const float* invA  = (PASS == 1) ? g_inv1  : g_inv2;

    // ---- weights: fp32 -> bf16 hi/lo images, staged in-kernel ----
    for (int i = tid; i < 5*4096; i += 256) {
        int v = i >> 12, oi = i & 4095;
        float w = (v == 0) ? Wc[oi] : Wk[oi*4 + (v-1)];
        __nv_bfloat16 hi = __float2bfloat16(w);
        __nv_bfloat16 lo = __float2bfloat16(w - __bfloat162float(hi));
        int oc = oi >> 6, ic = oi & 63;
        *(__nv_bfloat16*)(smraw + W_W + (v*2  )*8192 + oc*128 + ic*2) = hi;
        *(__nv_bfloat16*)(smraw + W_W + (v*2+1)*8192 + oc*128 + ic*2) = lo;
    }
    if (tid < 64) {
        int grp = tid >> 3;
        float m = meanA[b*8+grp], iv = invA[b*8+grp];
        float sc = iv * Ga[tid];
        sScale[tid] = sc;
        sShift[tid] = Be[tid] - m * sc;
        sBias[tid]  = Bi[tid];
        if (PASS == 2) {
            float ivs = g_invs[b*8+grp];
            float gsc = Gs[tid] * ivs;
            sB2[tid] = gsc;
            sB3[tid] = BeS[tid] - g_means[b*8+grp] * gsc;
        }
    }
    __syncthreads();   // scale/shift ready for staging below

    // ---- center staging: [px][ic] bf16 hi/lo rows of 128B, normalized+relu ----
    for (int i = tid; i < 2048; i += 256) {
        int ic = i >> 5, p4 = (i & 31) * 4;
        float4 v = *(const float4*)(same_base + (size_t)ic*NPIX + (size_t)y*WW + x0 + p4);
        float sc = sScale[ic], sf = sShift[ic];
        float vals[4] = {v.x, v.y, v.z, v.w};
        #pragma unroll
        for (int j = 0; j < 4; ++j) {
            int px = p4 + j;
            uint32_t off = (uint32_t)px*128 + ic*2;
            float nv = fmaxf(fmaf(vals[j], sc, sf), 0.f);
            __nv_bfloat16 h = __float2bfloat16(nv);
            __nv_bfloat16 l = __float2bfloat16(nv - __bfloat162float(h));
            *(__nv_bfloat16*)(smraw + W_CEN_H + off) = h;
            *(__nv_bfloat16*)(smraw + W_CEN_L + off) = l;
        }
    }
    // ---- cross staging: rows (dy*CR_STRIDE + j), j in [0,129), normalized+relu ----
    {
        int pair = tid >> 1, dy = pair >> 6, ic = pair & 63;
        int j0 = (tid & 1) * 65;
        int yy = y + cs - 1 + dy;
        int gx0 = x0 + cs - 1;
        float sc = sScale[ic], sf = sShift[ic];
        bool yok = ((unsigned)yy < HH);
        const float* srow = cross_base + (size_t)ic*NPIX + (size_t)(yok ? yy : 0)*WW;
        for (int jj = 0; jj < 65; ++jj) {
            int j = j0 + jj;
            if (j >= 129) break;
            int gx = gx0 + j;
            float v = 0.f;
            if (yok && (unsigned)gx < WW)
                v = fmaxf(fmaf(__ldg(srow + gx), sc, sf), 0.f);
            uint32_t off = (uint32_t)(dy*CR_STRIDE + j)*128 + ic*2;
            __nv_bfloat16 h = __float2bfloat16(v);
            __nv_bfloat16 l = __float2bfloat16(v - __bfloat162float(h));
            *(__nv_bfloat16*)(smraw + W_CRS_H + off) = h;
            *(__nv_bfloat16*)(smraw + W_CRS_L + off) = l;
        }
    }
    __syncthreads();

    // ---- wmma compute: per warp, 4 tiles of (16 oc x 16 px) ----
    wmma::fragment<wmma::matrix_a, 16, 16, 16, __nv_bfloat16, wmma::row_major> aH, aL;
    wmma::fragment<wmma::matrix_b, 16, 16, 16, __nv_bfloat16, wmma::col_major> bH, bL;
    wmma::fragment<wmma::accumulator, 16, 16, 16, float> acc;
    float* cst = (float*)(smraw + W_CST + warp*1280);

    for (int t = warp; t < 32; t += 8) {
        int octile = t >> 3, pxtile = t & 7;
        wmma::fill_fragment(acc, 0.f);

        #pragma unroll
        for (int v = 0; v < 5; ++v) {
            const char* bHb; const char* bLb; int rowbase;
            if (v == 0) {
                bHb = smraw + W_CEN_H; bLb = smraw + W_CEN_L;
                rowbase = pxtile*16;
            } else {
                int dy = (v-1) >> 1, dx = (v-1) & 1;
                bHb = smraw + W_CRS_H; bLb = smraw + W_CRS_L;
                rowbase = dy*CR_STRIDE + pxtile*16 + dx;
            }
            const char* wHb = smraw + W_W + (v*2)*8192;
            const char* wLb = wHb + 8192;
            #pragma unroll
            for (int kc = 0; kc < 4; ++kc) {
                wmma::load_matrix_sync(aH, (const __nv_bfloat16*)(wHb + octile*16*128 + kc*32), 64);
                wmma::load_matrix_sync(aL, (const __nv_bfloat16*)(wLb + octile*16*128 + kc*32), 64);
                wmma::load_matrix_sync(bH, (const __nv_bfloat16*)(bHb + rowbase*128 + kc*32), 64);
                wmma::load_matrix_sync(bL, (const __nv_bfloat16*)(bLb + rowbase*128 + kc*32), 64);
                wmma::mma_sync(acc, aH, bH, acc);
                wmma::mma_sync(acc, aH, bL, acc);
                wmma::mma_sync(acc, aL, bH, acc);
            }
        }

        __syncwarp();
        wmma::store_matrix_sync(cst, acc, 20, wmma::mem_row_major);
        __syncwarp();

        // epilogue: lane pair per oc row; lane covers 8 consecutive px
        int r0 = lane >> 1, cb8 = (lane & 1) * 8;
        int oc = octile*16 + r0;
        int pxb = pxtile*16 + cb8;
        float bv = sBias[oc];
        float vals[8];
        #pragma unroll
        for (int j = 0; j < 8; ++j) vals[j] = cst[r0*20 + cb8 + j] + bv;

        size_t goff = (size_t)y * WW + x0 + pxb;
        if (PASS == 1) {
            float* tp = &g_t[cs][b][oc][0][0] + goff;
            *(float4*)tp       = make_float4(vals[0], vals[1], vals[2], vals[3]);
            *(float4*)(tp + 4) = make_float4(vals[4], vals[5], vals[6], vals[7]);
            float s = 0.f, q = 0.f;
            #pragma unroll
            for (int j = 0; j < 8; ++j) { s += vals[j]; q += vals[j]*vals[j]; }
            #pragma unroll
            for (int off = 8; off; off >>= 1) {          // reduce within 16-lane halves
                s += __shfl_xor_sync(0xffffffffu, s, off);
                q += __shfl_xor_sync(0xffffffffu, q, off);
            }
            if ((lane & 15) == 0) {
                int gi = b*8 + octile*2 + (lane >> 4);
                atomicAdd(&g_sum_t[gi], s);
                atomicAdd(&g_ssq_t[gi], q);
            }
        } else {
            const float* sp = &g_s[cs][b][oc][0][0] + goff;
            float4 s1 = *(const float4*)sp;
            float4 s2 = *(const float4*)(sp + 4);
            float gc = sB2[oc], gh = sB3[oc];
            float4 o1, o2;
            o1.x = vals[0] + fmaf(s1.x, gc, gh);
            o1.y = vals[1] + fmaf(s1.y, gc, gh);
            o1.z = vals[2] + fmaf(s1.z, gc, gh);
            o1.w = vals[3] + fmaf(s1.w, gc, gh);
            o2.x = vals[4] + fmaf(s2.x, gc, gh);
            o2.y = vals[5] + fmaf(s2.y, gc, gh);
            o2.z = vals[6] + fmaf(s2.z, gc, gh);
            o2.w = vals[7] + fmaf(s2.w, gc, gh);
            float* op = Out + ((size_t)(cs*BB + b)*CC + oc)*NPIX + goff;
            *(float4*)op       = o1;
            *(float4*)(op + 4) = o2;
        }
        __syncwarp();
    }
}

// ---------------- launch ----------------
extern "C" void kernel_launch(void* const* d_in, const int* in_sizes, int n_in,
                              void* d_out, int out_size) {
    const float* x0      = (const float*)d_in[0];
    const float* x1      = (const float*)d_in[1];
    const float* g1      = (const float*)d_in[2];
    const float* b1      = (const float*)d_in[3];
    const float* w1c     = (const float*)d_in[4];
    const float* w1k     = (const float*)d_in[5];
    const float* bias1   = (const float*)d_in[6];
    const float* g2      = (const float*)d_in[7];
    const float* b2      = (const float*)d_in[8];
    const float* w2c     = (const float*)d_in[9];
    const float* w2k     = (const float*)d_in[10];
    const float* bias2   = (const float*)d_in[11];
    const float* wskip   = (const float*)d_in[12];
    const float* bskip   = (const float*)d_in[13];
    const float* gskip   = (const float*)d_in[14];
    const float* betask  = (const float*)d_in[15];

    cudaFuncSetAttribute(conv_w_k<1>, cudaFuncAttributeMaxDynamicSharedMemorySize, W_TOTAL);
    cudaFuncSetAttribute(conv_w_k<2>, cudaFuncAttributeMaxDynamicSharedMemorySize, W_TOTAL);

    zero_stats_k<<<1, 128>>>();
    skip_k<<<dim3(16, 32, 8), 256>>>(x0, x1, wskip, bskip);   // x-stats, s, s-stats
    finalize1_k<<<1, 32>>>();

    dim3 grid(2, 256, 4);   // z = b + 2*cs
    conv_w_k<1><<<grid, 256, W_TOTAL>>>(x0, x1, w1c, w1k, bias1, g1, b1,
                                        nullptr, nullptr, nullptr);
    finalize2_k<<<1, 64>>>();
    conv_w_k<2><<<grid, 256, W_TOTAL>>>(nullptr, nullptr, w2c, w2k, bias2, g2, b2,
                                        gskip, betask, (float*)d_out);
    (void)in_sizes; (void)n_in; (void)out_size;
}

// round 13
// speedup vs baseline: 1.1023x; 1.1023x over previous
#include <cuda_runtime.h>
#include <cuda_bf16.h>
#include <mma.h>
#include <cstdint>
using namespace nvcuda;

#define HH 256
#define WW 256
#define BB 2
#define CC 64
#define EPSV 1e-5f
#define NPIX (HH*WW)
#define NGRP 16
#define NELEM_GRP (8*NPIX*2)
#define YB 8

// ---------------- scratch ----------------
__device__ float g_t[2][BB][CC][HH][WW];
__device__ float g_s[2][BB][CC][HH][WW];
__device__ float g_sum_x[NGRP], g_ssq_x[NGRP];
__device__ float g_sum_t[NGRP], g_ssq_t[NGRP];
__device__ float g_sum_s[NGRP], g_ssq_s[NGRP];
__device__ float g_mean1[NGRP], g_inv1[NGRP];
__device__ float g_mean2[NGRP], g_inv2[NGRP];
__device__ float g_means[NGRP], g_invs[NGRP];
__device__ __nv_bfloat16 g_wb1[10*4096];
__device__ __nv_bfloat16 g_wb2[10*4096];

__device__ __forceinline__ uint32_t smem_u32(const void* p) {
    uint32_t a;
    asm("{ .reg .u64 t; cvta.to.shared.u64 t, %1; cvt.u32.u64 %0, t; }" : "=r"(a) : "l"(p));
    return a;
}
#define CP16(dst, src) asm volatile("cp.async.ca.shared.global [%0], [%1], 16;" :: "r"(dst), "l"(src))
#define CP_COMMIT() asm volatile("cp.async.commit_group;")
#define CP_WAIT0()  asm volatile("cp.async.wait_group 0;" ::: "memory")

// ---------------- small kernels ----------------
__global__ void zero_stats_k() {
    int i = threadIdx.x;
    if (i < NGRP) {
        g_sum_x[i] = 0.f; g_ssq_x[i] = 0.f;
        g_sum_t[i] = 0.f; g_ssq_t[i] = 0.f;
        g_sum_s[i] = 0.f; g_ssq_s[i] = 0.f;
    }
}

__global__ void prep_w_k(const float* __restrict__ w1c, const float* __restrict__ w1k,
                         const float* __restrict__ w2c, const float* __restrict__ w2k) {
    int idx = blockIdx.x * 256 + threadIdx.x;
    const int P1 = 10 * 4096;
    __nv_bfloat16* dst; int mat, oi; float w;
    if (idx < P1) {
        mat = idx >> 12; oi = idx & 4095;
        int v = mat >> 1;
        w = (v == 0) ? w1c[oi] : w1k[oi*4 + (v-1)];
        dst = g_wb1 + mat * 4096;
    } else {
        idx -= P1;
        if (idx >= P1) return;
        mat = idx >> 12; oi = idx & 4095;
        int v = mat >> 1;
        w = (v == 0) ? w2c[oi] : w2k[oi*4 + (v-1)];
        dst = g_wb2 + mat * 4096;
    }
    __nv_bfloat16 hi = __float2bfloat16(w);
    __nv_bfloat16 lo = __float2bfloat16(w - __bfloat162float(hi));
    dst[oi] = (mat & 1) ? lo : hi;
}

__global__ void finalize1_k() {
    int i = threadIdx.x;
    if (i < NGRP) {
        float n = (float)NELEM_GRP;
        float m = g_sum_x[i] / n;
        float v = g_ssq_x[i] / n - m*m;
        g_mean1[i] = m; g_inv1[i] = rsqrtf(v + EPSV);
    }
}

__global__ void finalize2_k() {
    int i = threadIdx.x;
    float n = (float)NELEM_GRP;
    if (i < NGRP) {
        float m = g_sum_t[i] / n;
        float v = g_ssq_t[i] / n - m*m;
        g_mean2[i] = m; g_inv2[i] = rsqrtf(v + EPSV);
    } else if (i < 2*NGRP) {
        int j = i - NGRP;
        float m = g_sum_s[j] / n;
        float v = g_ssq_s[j] / n - m*m;
        g_means[j] = m; g_invs[j] = rsqrtf(v + EPSV);
    }
}

// ---------------- skip kernel (proven) ----------------
__global__ __launch_bounds__(256, 4)
void skip_k(const float* __restrict__ x0, const float* __restrict__ x1,
            const float* __restrict__ Ws, const float* __restrict__ Bs)
{
    __shared__ float sW[32*64];
    __shared__ float sX[2048];

    int tid = threadIdx.x, warp = tid >> 5, lane = tid & 31;
    int r = lane >> 2, cb = (lane & 3) * 4;
    int z = blockIdx.z; int b = z & 1, cs = (z >> 1) & 1, half = z >> 2;
    int oc0 = half * 32 + warp * 4;
    int y0 = blockIdx.y * 8, xb = blockIdx.x * 16;

    const float* xbase = (cs ? x1 : x0) + (size_t)b * CC * NPIX;

    for (int idx = tid; idx < 2048; idx += 256)
        sW[idx] = Ws[(size_t)(half*32 + (idx >> 6)) * 64 + (idx & 63)];

    float acc[4][4];
    #pragma unroll
    for (int o = 0; o < 4; ++o) {
        float bv = Bs[oc0 + o];
        #pragma unroll
        for (int p = 0; p < 4; ++p) acc[o][p] = bv;
    }

    for (int icc = 0; icc < 4; ++icc) {
        __syncthreads();
        for (int idx = tid; idx < 512; idx += 256) {
            int ic = idx >> 5, q = idx & 31;
            int row = q >> 2, c4 = (q & 3) * 4;
            const float* src = xbase + (size_t)(icc*16+ic)*NPIX
                               + (size_t)(y0+row)*WW + xb + c4;
            *(float4*)&sX[ic*128 + row*16 + c4] = *(const float4*)src;
        }
        __syncthreads();

        float xs0 = 0.f, xq0 = 0.f, xs1 = 0.f, xq1 = 0.f;
        bool do_stats = (half == 0) && (warp == 0);
        #pragma unroll 4
        for (int ic = 0; ic < 16; ++ic) {
            int gic = icc*16 + ic;
            float4 rv = *(float4*)&sX[ic*128 + r*16 + cb];
            if (do_stats) {
                float s = (rv.x + rv.y) + (rv.z + rv.w);
                float q = (rv.x*rv.x + rv.y*rv.y) + (rv.z*rv.z + rv.w*rv.w);
                if (ic < 8) { xs0 += s; xq0 += q; } else { xs1 += s; xq1 += q; }
            }
            #pragma unroll
            for (int o = 0; o < 4; ++o) {
                float w = sW[(warp*4 + o)*64 + gic];
                acc[o][0] = fmaf(w, rv.x, acc[o][0]);
                acc[o][1] = fmaf(w, rv.y, acc[o][1]);
                acc[o][2] = fmaf(w, rv.z, acc[o][2]);
                acc[o][3] = fmaf(w, rv.w, acc[o][3]);
            }
        }
        if (do_stats) {
            #pragma unroll
            for (int off = 16; off; off >>= 1) {
                xs0 += __shfl_xor_sync(0xffffffffu, xs0, off);
                xq0 += __shfl_xor_sync(0xffffffffu, xq0, off);
                xs1 += __shfl_xor_sync(0xffffffffu, xs1, off);
                xq1 += __shfl_xor_sync(0xffffffffu, xq1, off);
            }
            if (lane == 0) {
                atomicAdd(&g_sum_x[b*8 + icc*2],     xs0);
                atomicAdd(&g_ssq_x[b*8 + icc*2],     xq0);
                atomicAdd(&g_sum_x[b*8 + icc*2 + 1], xs1);
                atomicAdd(&g_ssq_x[b*8 + icc*2 + 1], xq1);
            }
        }
    }

    size_t pixoff = (size_t)(y0 + r) * WW + xb + cb;
    float sv = 0.f, ssv = 0.f;
    #pragma unroll
    for (int o = 0; o < 4; ++o) {
        float* sp = &g_s[cs][b][oc0 + o][0][0] + pixoff;
        *(float4*)sp = make_float4(acc[o][0], acc[o][1], acc[o][2], acc[o][3]);
        #pragma unroll
        for (int p = 0; p < 4; ++p) { sv += acc[o][p]; ssv += acc[o][p]*acc[o][p]; }
    }
    #pragma unroll
    for (int off = 16; off; off >>= 1) {
        sv  += __shfl_xor_sync(0xffffffffu, sv,  off);
        ssv += __shfl_xor_sync(0xffffffffu, ssv, off);
    }
    if (lane == 0) {
        int gi = b*8 + (oc0 >> 3);
        atomicAdd(&g_sum_s[gi], sv); atomicAdd(&g_ssq_s[gi], ssv);
    }
}

// ---------------- wmma conv kernel (multi-row, cp.async weights) ----------------
#define W_MISC   0
#define W_W      1280
#define W_CEN_H  83200
#define W_CEN_L  99584
#define W_CRS_H  115968
#define W_CRS_L  149248
#define W_CST    182528
#define W_TOTAL  203008
#define CRS_SLOT 16640

template<int PASS>
__global__ __launch_bounds__(512, 1)
void conv_w_k(const float* __restrict__ in0, const float* __restrict__ in1,
              const float* __restrict__ Bi,
              const float* __restrict__ Ga, const float* __restrict__ Be,
              const float* __restrict__ Gs, const float* __restrict__ BeS,
              float* __restrict__ Out)
{
    extern __shared__ __align__(128) char smraw[];
    float* sScale = (float*)(smraw + W_MISC);
    float* sShift = sScale + 64;
    float* sBias  = sShift + 64;
    float* sB2    = sBias + 64;
    float* sB3    = sB2 + 64;

    int tid = threadIdx.x, warp = tid >> 5, lane = tid & 31;
    int bc = blockIdx.z; int b = bc & 1, cs = bc >> 1;
    int y0 = blockIdx.y * YB;
    int x0 = blockIdx.x * 128;

    const float* same_base;
    const float* cross_base;
    if (PASS == 1) {
        same_base  = (cs ? in1 : in0) + (size_t)b * CC * NPIX;
        cross_base = (cs ? in0 : in1) + (size_t)b * CC * NPIX;
    } else {
        same_base  = &g_t[cs][b][0][0][0];
        cross_base = &g_t[cs ^ 1][b][0][0][0];
    }
    const float* meanA = (PASS == 1) ? g_mean1 : g_mean2;
    const float* invA  = (PASS == 1) ? g_inv1  : g_inv2;

    // weights: one cp.async copy per CTA (dense bf16 hi/lo, layout identical to round 12)
    {
        uint32_t sb = smem_u32(smraw);
        const char* wsrc = (const char*)((PASS == 1) ? g_wb1 : g_wb2);
        for (int i = tid; i < 5120; i += 512)
            CP16(sb + W_W + i*16, wsrc + (size_t)i*16);
        CP_COMMIT();
    }
    if (tid < 64) {
        int grp = tid >> 3;
        float m = meanA[b*8+grp], iv = invA[b*8+grp];
        float sc = iv * Ga[tid];
        sScale[tid] = sc;
        sShift[tid] = Be[tid] - m * sc;
        sBias[tid]  = Bi[tid];
        if (PASS == 2) {
            float ivs = g_invs[b*8+grp];
            float gsc = Gs[tid] * ivs;
            sB2[tid] = gsc;
            sB3[tid] = BeS[tid] - g_means[b*8+grp] * gsc;
        }
    }
    __syncthreads();

    wmma::fragment<wmma::matrix_a, 16, 16, 16, __nv_bfloat16, wmma::row_major> aH, aL;
    wmma::fragment<wmma::matrix_b, 16, 16, 16, __nv_bfloat16, wmma::col_major> bH, bL;
    wmma::fragment<wmma::accumulator, 16, 16, 16, float> acc;
    float* cst = (float*)(smraw + W_CST + warp*1280);

    int ic_t = tid & 63;
    int q_t  = tid >> 6;             // 0..7
    float sc_t = sScale[ic_t], sf_t = sShift[ic_t];
    const float* cen_ic = same_base  + (size_t)ic_t*NPIX;
    const float* crs_ic = cross_base + (size_t)ic_t*NPIX;
    int gx0 = x0 + cs - 1;

    // stage one cross row yy into its parity slot
    auto stage_cross = [&](int yy) {
        int slot = yy & 1;
        char* dH = smraw + W_CRS_H + slot*CRS_SLOT;
        char* dL = smraw + W_CRS_L + slot*CRS_SLOT;
        bool yok = ((unsigned)yy < HH);
        const float* srow = crs_ic + (size_t)(yok ? yy : 0)*WW;
        #pragma unroll 4
        for (int m = 0; m < 17; ++m) {
            int j = q_t*17 + m;
            if (j >= 130) break;
            int gx = gx0 + j;
            float v = 0.f;
            if (yok && (unsigned)gx < WW)
                v = fmaxf(fmaf(__ldg(srow + gx), sc_t, sf_t), 0.f);
            __nv_bfloat16 h = __float2bfloat16(v);
            __nv_bfloat16 l = __float2bfloat16(v - __bfloat162float(h));
            *(__nv_bfloat16*)(dH + j*128 + ic_t*2) = h;
            *(__nv_bfloat16*)(dL + j*128 + ic_t*2) = l;
        }
    };

    stage_cross(y0 + cs - 1);
    stage_cross(y0 + cs);
    CP_WAIT0();

    for (int i = 0; i < YB; ++i) {
        int y = y0 + i;
        // center staging: px = q_t*16 + k*4 + j, one ic per thread
        {
            const float* src = cen_ic + (size_t)y*WW + x0 + q_t*16;
            #pragma unroll
            for (int k = 0; k < 4; ++k) {
                float4 v = *(const float4*)(src + k*4);
                float vals[4] = {v.x, v.y, v.z, v.w};
                #pragma unroll
                for (int j = 0; j < 4; ++j) {
                    float nv = fmaxf(fmaf(vals[j], sc_t, sf_t), 0.f);
                    __nv_bfloat16 h = __float2bfloat16(nv);
                    __nv_bfloat16 l = __float2bfloat16(nv - __bfloat162float(h));
                    int p = q_t*16 + k*4 + j;
                    *(__nv_bfloat16*)(smraw + W_CEN_H + p*128 + ic_t*2) = h;
                    *(__nv_bfloat16*)(smraw + W_CEN_L + p*128 + ic_t*2) = l;
                }
            }
        }
        if (i > 0) stage_cross(y + cs);
        __syncthreads();

        for (int t = warp; t < 32; t += 16) {
            int octile = t >> 3, pxtile = t & 7;
            wmma::fill_fragment(acc, 0.f);
            #pragma unroll
            for (int v = 0; v < 5; ++v) {
                const char* bHb; const char* bLb; int rowoff;
                if (v == 0) {
                    bHb = smraw + W_CEN_H; bLb = smraw + W_CEN_L;
                    rowoff = pxtile*16;
                } else {
                    int dy = (v-1) >> 1, dx = (v-1) & 1;
                    int slot = (y + cs - 1 + dy) & 1;
                    bHb = smraw + W_CRS_H + slot*CRS_SLOT;
                    bLb = smraw + W_CRS_L + slot*CRS_SLOT;
                    rowoff = pxtile*16 + dx;
                }
                const char* wHb = smraw + W_W + (v*2)*8192;
                const char* wLb = wHb + 8192;
                #pragma unroll
                for (int kc = 0; kc < 4; ++kc) {
                    wmma::load_matrix_sync(aH, (const __nv_bfloat16*)(wHb + octile*2048 + kc*32), 64);
                    wmma::load_matrix_sync(aL, (const __nv_bfloat16*)(wLb + octile*2048 + kc*32), 64);
                    wmma::load_matrix_sync(bH, (const __nv_bfloat16*)(bHb + rowoff*128 + kc*32), 64);
                    wmma::load_matrix_sync(bL, (const __nv_bfloat16*)(bLb + rowoff*128 + kc*32), 64);
                    wmma::mma_sync(acc, aH, bH, acc);
                    wmma::mma_sync(acc, aH, bL, acc);
                    wmma::mma_sync(acc, aL, bH, acc);
                }
            }

            __syncwarp();
            wmma::store_matrix_sync(cst, acc, 20, wmma::mem_row_major);
            __syncwarp();

            int r0 = lane >> 1, cb8 = (lane & 1) * 8;
            int oc = octile*16 + r0;
            int pxb = pxtile*16 + cb8;
            float bv = sBias[oc];
            float vals[8];
            #pragma unroll
            for (int j = 0; j < 8; ++j) vals[j] = cst[r0*20 + cb8 + j] + bv;

            size_t goff = (size_t)y * WW + x0 + pxb;
            if (PASS == 1) {
                float* tp = &g_t[cs][b][oc][0][0] + goff;
                *(float4*)tp       = make_float4(vals[0], vals[1], vals[2], vals[3]);
                *(float4*)(tp + 4) = make_float4(vals[4], vals[5], vals[6], vals[7]);
                float s = 0.f, q = 0.f;
                #pragma unroll
                for (int j = 0; j < 8; ++j) { s += vals[j]; q += vals[j]*vals[j]; }
                #pragma unroll
                for (int off = 8; off; off >>= 1) {
                    s += __shfl_xor_sync(0xffffffffu, s, off);
                    q += __shfl_xor_sync(0xffffffffu, q, off);
                }
                if ((lane & 15) == 0) {
                    int gi = b*8 + octile*2 + (lane >> 4);
                    atomicAdd(&g_sum_t[gi], s);
                    atomicAdd(&g_ssq_t[gi], q);
                }
            } else {
                const float* sp = &g_s[cs][b][oc][0][0] + goff;
                float4 s1 = *(const float4*)sp;
                float4 s2 = *(const float4*)(sp + 4);
                float gc = sB2[oc], gh = sB3[oc];
                float4 o1, o2;
                o1.x = vals[0] + fmaf(s1.x, gc, gh);
                o1.y = vals[1] + fmaf(s1.y, gc, gh);
                o1.z = vals[2] + fmaf(s1.z, gc, gh);
                o1.w = vals[3] + fmaf(s1.w, gc, gh);
                o2.x = vals[4] + fmaf(s2.x, gc, gh);
                o2.y = vals[5] + fmaf(s2.y, gc, gh);
                o2.z = vals[6] + fmaf(s2.z, gc, gh);
                o2.w = vals[7] + fmaf(s2.w, gc, gh);
                float* op = Out + ((size_t)(cs*BB + b)*CC + oc)*NPIX + goff;
                *(float4*)op       = o1;
                *(float4*)(op + 4) = o2;
            }
            __syncwarp();
        }
        __syncthreads();
    }
}

// ---------------- launch ----------------
extern "C" void kernel_launch(void* const* d_in, const int* in_sizes, int n_in,
                              void* d_out, int out_size) {
    const float* x0      = (const float*)d_in[0];
    const float* x1      = (const float*)d_in[1];
    const float* g1      = (const float*)d_in[2];
    const float* b1      = (const float*)d_in[3];
    const float* w1c     = (const float*)d_in[4];
    const float* w1k     = (const float*)d_in[5];
    const float* bias1   = (const float*)d_in[6];
    const float* g2      = (const float*)d_in[7];
    const float* b2      = (const float*)d_in[8];
    const float* w2c     = (const float*)d_in[9];
    const float* w2k     = (const float*)d_in[10];
    const float* bias2   = (const float*)d_in[11];
    const float* wskip   = (const float*)d_in[12];
    const float* bskip   = (const float*)d_in[13];
    const float* gskip   = (const float*)d_in[14];
    const float* betask  = (const float*)d_in[15];

    cudaFuncSetAttribute(conv_w_k<1>, cudaFuncAttributeMaxDynamicSharedMemorySize, W_TOTAL);
    cudaFuncSetAttribute(conv_w_k<2>, cudaFuncAttributeMaxDynamicSharedMemorySize, W_TOTAL);

    zero_stats_k<<<1, 128>>>();
    prep_w_k<<<320, 256>>>(w1c, w1k, w2c, w2k);
    skip_k<<<dim3(16, 32, 8), 256>>>(x0, x1, wskip, bskip);
    finalize1_k<<<1, 32>>>();

    dim3 grid(2, 32, 4);   // z = b + 2*cs
    conv_w_k<1><<<grid, 512, W_TOTAL>>>(x0, x1, bias1, g1, b1,
                                        nullptr, nullptr, nullptr);
    finalize2_k<<<1, 64>>>();
    conv_w_k<2><<<grid, 512, W_TOTAL>>>(nullptr, nullptr, bias2, g2, b2,
                                        gskip, betask, (float*)d_out);
    (void)in_sizes; (void)n_in; (void)out_size;
}

// round 15
// speedup vs baseline: 2.9719x; 2.6961x over previous
#include <cuda_runtime.h>
#include <cuda_fp16.h>
#include <mma.h>
#include <cstdint>
using namespace nvcuda;

#define HH 256
#define WW 256
#define BB 2
#define CC 64
#define EPSV 1e-5f
#define NPIX (HH*WW)
#define NGRP 16
#define NELEM_GRP (8*NPIX*2)
#define YB 8

// ---------------- scratch ----------------
__device__ float g_t[2][BB][CC][HH][WW];
__device__ float g_s[2][BB][CC][HH][WW];
__device__ float g_sum_x[NGRP], g_ssq_x[NGRP];
__device__ float g_sum_t[NGRP], g_ssq_t[NGRP];
__device__ float g_sum_s[NGRP], g_ssq_s[NGRP];
__device__ float g_mean1[NGRP], g_inv1[NGRP];
__device__ float g_mean2[NGRP], g_inv2[NGRP];
__device__ float g_means[NGRP], g_invs[NGRP];
// fp16 weights: hi exact-rounded, lo = (w - hi) * 1024 (subnormal-safe)
__device__ __half g_w1h[5*4096], g_w1l[5*4096];
__device__ __half g_w2h[5*4096], g_w2l[5*4096];

__device__ __forceinline__ uint32_t smem_u32(const void* p) {
    uint32_t a;
    asm("{ .reg .u64 t; cvta.to.shared.u64 t, %1; cvt.u32.u64 %0, t; }" : "=r"(a) : "l"(p));
    return a;
}
#define CP16(dst, src) asm volatile("cp.async.ca.shared.global [%0], [%1], 16;" :: "r"(dst), "l"(src))
#define CP_COMMIT() asm volatile("cp.async.commit_group;")
#define CP_WAIT0()  asm volatile("cp.async.wait_group 0;" ::: "memory")

// ---------------- small kernels ----------------
__global__ void zero_stats_k() {
    int i = threadIdx.x;
    if (i < NGRP) {
        g_sum_x[i] = 0.f; g_ssq_x[i] = 0.f;
        g_sum_t[i] = 0.f; g_ssq_t[i] = 0.f;
        g_sum_s[i] = 0.f; g_ssq_s[i] = 0.f;
    }
}

__global__ void prep_w_k(const float* __restrict__ w1c, const float* __restrict__ w1k,
                         const float* __restrict__ w2c, const float* __restrict__ w2k) {
    int idx = blockIdx.x * 256 + threadIdx.x;
    if (idx >= 2*5*4096) return;
    int pass = idx >= 5*4096;
    int rem = idx - pass*5*4096;
    int v = rem >> 12, oi = rem & 4095;
    float w = pass ? ((v == 0) ? w2c[oi] : w2k[oi*4 + (v-1)])
                   : ((v == 0) ? w1c[oi] : w1k[oi*4 + (v-1)]);
    __half hi = __float2half(w);
    __half lo = __float2half((w - __half2float(hi)) * 1024.f);
    if (pass) { g_w2h[rem] = hi; g_w2l[rem] = lo; }
    else      { g_w1h[rem] = hi; g_w1l[rem] = lo; }
}

__global__ void finalize1_k() {
    int i = threadIdx.x;
    if (i < NGRP) {
        float n = (float)NELEM_GRP;
        float m = g_sum_x[i] / n;
        float v = g_ssq_x[i] / n - m*m;
        g_mean1[i] = m; g_inv1[i] = rsqrtf(v + EPSV);
    }
}

__global__ void finalize2_k() {
    int i = threadIdx.x;
    float n = (float)NELEM_GRP;
    if (i < NGRP) {
        float m = g_sum_t[i] / n;
        float v = g_ssq_t[i] / n - m*m;
        g_mean2[i] = m; g_inv2[i] = rsqrtf(v + EPSV);
    } else if (i < 2*NGRP) {
        int j = i - NGRP;
        float m = g_sum_s[j] / n;
        float v = g_ssq_s[j] / n - m*m;
        g_means[j] = m; g_invs[j] = rsqrtf(v + EPSV);
    }
}

// ---------------- skip kernel (proven) ----------------
__global__ __launch_bounds__(256, 4)
void skip_k(const float* __restrict__ x0, const float* __restrict__ x1,
            const float* __restrict__ Ws, const float* __restrict__ Bs)
{
    __shared__ float sW[32*64];
    __shared__ float sX[2048];

    int tid = threadIdx.x, warp = tid >> 5, lane = tid & 31;
    int r = lane >> 2, cb = (lane & 3) * 4;
    int z = blockIdx.z; int b = z & 1, cs = (z >> 1) & 1, half = z >> 2;
    int oc0 = half * 32 + warp * 4;
    int y0 = blockIdx.y * 8, xb = blockIdx.x * 16;

    const float* xbase = (cs ? x1 : x0) + (size_t)b * CC * NPIX;

    for (int idx = tid; idx < 2048; idx += 256)
        sW[idx] = Ws[(size_t)(half*32 + (idx >> 6)) * 64 + (idx & 63)];

    float acc[4][4];
    #pragma unroll
    for (int o = 0; o < 4; ++o) {
        float bv = Bs[oc0 + o];
        #pragma unroll
        for (int p = 0; p < 4; ++p) acc[o][p] = bv;
    }

    for (int icc = 0; icc < 4; ++icc) {
        __syncthreads();
        for (int idx = tid; idx < 512; idx += 256) {
            int ic = idx >> 5, q = idx & 31;
            int row = q >> 2, c4 = (q & 3) * 4;
            const float* src = xbase + (size_t)(icc*16+ic)*NPIX
                               + (size_t)(y0+row)*WW + xb + c4;
            *(float4*)&sX[ic*128 + row*16 + c4] = *(const float4*)src;
        }
        __syncthreads();

        float xs0 = 0.f, xq0 = 0.f, xs1 = 0.f, xq1 = 0.f;
        bool do_stats = (half == 0) && (warp == 0);
        #pragma unroll 4
        for (int ic = 0; ic < 16; ++ic) {
            int gic = icc*16 + ic;
            float4 rv = *(float4*)&sX[ic*128 + r*16 + cb];
            if (do_stats) {
                float s = (rv.x + rv.y) + (rv.z + rv.w);
                float q = (rv.x*rv.x + rv.y*rv.y) + (rv.z*rv.z + rv.w*rv.w);
                if (ic < 8) { xs0 += s; xq0 += q; } else { xs1 += s; xq1 += q; }
            }
            #pragma unroll
            for (int o = 0; o < 4; ++o) {
                float w = sW[(warp*4 + o)*64 + gic];
                acc[o][0] = fmaf(w, rv.x, acc[o][0]);
                acc[o][1] = fmaf(w, rv.y, acc[o][1]);
                acc[o][2] = fmaf(w, rv.z, acc[o][2]);
                acc[o][3] = fmaf(w, rv.w, acc[o][3]);
            }
        }
        if (do_stats) {
            #pragma unroll
            for (int off = 16; off; off >>= 1) {
                xs0 += __shfl_xor_sync(0xffffffffu, xs0, off);
                xq0 += __shfl_xor_sync(0xffffffffu, xq0, off);
                xs1 += __shfl_xor_sync(0xffffffffu, xs1, off);
                xq1 += __shfl_xor_sync(0xffffffffu, xq1, off);
            }
            if (lane == 0) {
                atomicAdd(&g_sum_x[b*8 + icc*2],     xs0);
                atomicAdd(&g_ssq_x[b*8 + icc*2],     xq0);
                atomicAdd(&g_sum_x[b*8 + icc*2 + 1], xs1);
                atomicAdd(&g_ssq_x[b*8 + icc*2 + 1], xq1);
            }
        }
    }

    size_t pixoff = (size_t)(y0 + r) * WW + xb + cb;
    float sv = 0.f, ssv = 0.f;
    #pragma unroll
    for (int o = 0; o < 4; ++o) {
        float* sp = &g_s[cs][b][oc0 + o][0][0] + pixoff;
        *(float4*)sp = make_float4(acc[o][0], acc[o][1], acc[o][2], acc[o][3]);
        #pragma unroll
        for (int p = 0; p < 4; ++p) { sv += acc[o][p]; ssv += acc[o][p]*acc[o][p]; }
    }
    #pragma unroll
    for (int off = 16; off; off >>= 1) {
        sv  += __shfl_xor_sync(0xffffffffu, sv,  off);
        ssv += __shfl_xor_sync(0xffffffffu, ssv, off);
    }
    if (lane == 0) {
        int gi = b*8 + (oc0 >> 3);
        atomicAdd(&g_sum_s[gi], sv); atomicAdd(&g_ssq_s[gi], ssv);
    }
}

// ---------------- wmma conv kernel (fp16, [ic][px] rows of 272B, pre-shifted cross) ----------------
// grid (2, 32, 4); 512 thr = 16 warps; warp = octile(>>2) x pxquad(&3).
#define ROWB     272            // 136 halves; ldm=136 (mult of 8); 68-word stride -> conflict-free ldmatrix
#define W_MISC   0
#define W_WH     1280                      // 5*8192 = 40960
#define W_WL     42240                     // 40960
#define W_CEN    83200                     // 64 ic * 272 = 17408
#define W_CRS    100608                    // 2 slots * 2 shifts * 17408 = 69632
#define W_CST    170240                    // 16 warps * 1280
#define W_TOTAL  190720
#define CRS_SLOT 34816
#define CRS_SHFT 17408
#define LO_SCL   (1.f/1024.f)

template<int PASS>
__global__ __launch_bounds__(512, 1)
void conv_w_k(const float* __restrict__ in0, const float* __restrict__ in1,
              const float* __restrict__ Bi,
              const float* __restrict__ Ga, const float* __restrict__ Be,
              const float* __restrict__ Gs, const float* __restrict__ BeS,
              float* __restrict__ Out)
{
    extern __shared__ __align__(128) char smraw[];
    float* sScale = (float*)(smraw + W_MISC);
    float* sShift = sScale + 64;
    float* sBias  = sShift + 64;
    float* sB2    = sBias + 64;
    float* sB3    = sB2 + 64;

    int tid = threadIdx.x, warp = tid >> 5, lane = tid & 31;
    int bc = blockIdx.z; int b = bc & 1, cs = bc >> 1;
    int y0 = blockIdx.y * YB;
    int x0 = blockIdx.x * 128;

    const float* same_base;
    const float* cross_base;
    if (PASS == 1) {
        same_base  = (cs ? in1 : in0) + (size_t)b * CC * NPIX;
        cross_base = (cs ? in0 : in1) + (size_t)b * CC * NPIX;
    } else {
        same_base  = &g_t[cs][b][0][0][0];
        cross_base = &g_t[cs ^ 1][b][0][0][0];
    }
    const float* meanA = (PASS == 1) ? g_mean1 : g_mean2;
    const float* invA  = (PASS == 1) ? g_inv1  : g_inv2;

    // weights cp.async
    {
        uint32_t sb = smem_u32(smraw);
        const char* hsrc = (const char*)((PASS == 1) ? g_w1h : g_w2h);
        const char* lsrc = (const char*)((PASS == 1) ? g_w1l : g_w2l);
        for (int i = tid; i < 2560; i += 512) {
            CP16(sb + W_WH + i*16, hsrc + (size_t)i*16);
            CP16(sb + W_WL + i*16, lsrc + (size_t)i*16);
        }
        CP_COMMIT();
    }
    if (tid < 64) {
        int grp = tid >> 3;
        float m = meanA[b*8+grp], iv = invA[b*8+grp];
        float sc = iv * Ga[tid];
        sScale[tid] = sc;
        sShift[tid] = Be[tid] - m * sc;
        sBias[tid]  = Bi[tid];
        if (PASS == 2) {
            float ivs = g_invs[b*8+grp];
            float gsc = Gs[tid] * ivs;
            sB2[tid] = gsc;
            sB3[tid] = BeS[tid] - g_means[b*8+grp] * gsc;
        }
    }
    __syncthreads();

    wmma::fragment<wmma::matrix_a, 16, 16, 16, __half, wmma::row_major> aH, aL;
    wmma::fragment<wmma::matrix_b, 16, 16, 16, __half, wmma::row_major> b0, b1;
    wmma::fragment<wmma::accumulator, 16, 16, 16, float> cH0, cH1, cL0, cL1;
    float* cst = (float*)(smraw + W_CST + warp*1280);

    int gx0 = x0 + cs - 1;

    // stage one cross row into (slot, shift) buffers; warp owns 4 ic rows, lanes cover px.
    // D0[j] = src[j] (dx=0), D1[j] = src[j+1] (dx=1); both loads then use aligned noff=px0.
    auto stage_cross = [&](int yy) {
        int slot = yy & 1;
        char* d0 = smraw + W_CRS + slot*CRS_SLOT;
        char* d1 = d0 + CRS_SHFT;
        bool yok = ((unsigned)yy < HH);
        #pragma unroll
        for (int k = 0; k < 4; ++k) {
            int ic = warp*4 + k;
            float sc = sScale[ic], sf = sShift[ic];
            const float* srow = cross_base + (size_t)ic*NPIX + (size_t)(yok ? yy : 0)*WW;
            #pragma unroll
            for (int m = 0; m < 5; ++m) {
                int j = lane + m*32;          // source index 0..159 (used: 0..128)
                float v = 0.f;
                int gx = gx0 + j;
                if (yok && j < 130 && (unsigned)gx < WW)
                    v = fmaxf(fmaf(__ldg(srow + gx), sc, sf), 0.f);
                __half hv = __float2half(v);
                if (j < 136)          *(__half*)(d0 + ic*ROWB + j*2)     = hv;
                if (j >= 1 && j < 137) *(__half*)(d1 + ic*ROWB + (j-1)*2) = hv;
            }
        }
    };

    stage_cross(y0 + cs - 1);
    stage_cross(y0 + cs);
    CP_WAIT0();

    for (int i = 0; i < YB; ++i) {
        int y = y0 + i;
        // center staging: warp owns 4 ic rows, lanes cover 128 px via float4
        #pragma unroll
        for (int k = 0; k < 4; ++k) {
            int ic = warp*4 + k;
            float sc = sScale[ic], sf = sShift[ic];
            float4 v4 = *(const float4*)(same_base + (size_t)ic*NPIX + (size_t)y*WW + x0 + lane*4);
            __half2 h0 = __floats2half2_rn(fmaxf(fmaf(v4.x, sc, sf), 0.f),
                                           fmaxf(fmaf(v4.y, sc, sf), 0.f));
            __half2 h1 = __floats2half2_rn(fmaxf(fmaf(v4.z, sc, sf), 0.f),
                                           fmaxf(fmaf(v4.w, sc, sf), 0.f));
            uint32_t u0 = *(uint32_t*)&h0, u1 = *(uint32_t*)&h1;
            *(uint2*)(smraw + W_CEN + ic*ROWB + lane*8) = make_uint2(u0, u1);
        }
        if (i > 0) stage_cross(y + cs);
        __syncthreads();

        int octile = warp >> 2;
        int px0 = (warp & 3) * 32;
        wmma::fill_fragment(cH0, 0.f); wmma::fill_fragment(cH1, 0.f);
        wmma::fill_fragment(cL0, 0.f); wmma::fill_fragment(cL1, 0.f);

        #pragma unroll
        for (int v = 0; v < 5; ++v) {
            const char* bb;
            if (v == 0) {
                bb = smraw + W_CEN;
            } else {
                int dy = (v-1) >> 1, dx = (v-1) & 1;
                int slot = (y + cs - 1 + dy) & 1;
                bb = smraw + W_CRS + slot*CRS_SLOT + dx*CRS_SHFT;
            }
            const char* whb = smraw + W_WH + v*8192;
            const char* wlb = smraw + W_WL + v*8192;
            #pragma unroll
            for (int kc = 0; kc < 4; ++kc) {
                wmma::load_matrix_sync(aH, (const __half*)(whb + octile*2048 + kc*32), 64);
                wmma::load_matrix_sync(aL, (const __half*)(wlb + octile*2048 + kc*32), 64);
                wmma::load_matrix_sync(b0, (const __half*)(bb + kc*16*ROWB + px0*2), 136);
                wmma::load_matrix_sync(b1, (const __half*)(bb + kc*16*ROWB + (px0+16)*2), 136);
                wmma::mma_sync(cH0, aH, b0, cH0);
                wmma::mma_sync(cL0, aL, b0, cL0);
                wmma::mma_sync(cH1, aH, b1, cH1);
                wmma::mma_sync(cL1, aL, b1, cL1);
            }
        }
        #pragma unroll
        for (int e = 0; e < cH0.num_elements; ++e) {
            cH0.x[e] = fmaf(cL0.x[e], LO_SCL, cH0.x[e]);
            cH1.x[e] = fmaf(cL1.x[e], LO_SCL, cH1.x[e]);
        }

        #pragma unroll
        for (int t = 0; t < 2; ++t) {
            __syncwarp();
            wmma::store_matrix_sync(cst, (t == 0) ? cH0 : cH1, 20, wmma::mem_row_major);
            __syncwarp();

            int r0 = lane >> 1, cb8 = (lane & 1) * 8;
            int oc = octile*16 + r0;
            int pxb = px0 + t*16 + cb8;
            float bv = sBias[oc];
            float vals[8];
            #pragma unroll
            for (int j = 0; j < 8; ++j) vals[j] = cst[r0*20 + cb8 + j] + bv;

            size_t goff = (size_t)y * WW + x0 + pxb;
            if (PASS == 1) {
                float* tp = &g_t[cs][b][oc][0][0] + goff;
                *(float4*)tp       = make_float4(vals[0], vals[1], vals[2], vals[3]);
                *(float4*)(tp + 4) = make_float4(vals[4], vals[5], vals[6], vals[7]);
                float s = 0.f, q = 0.f;
                #pragma unroll
                for (int j = 0; j < 8; ++j) { s += vals[j]; q += vals[j]*vals[j]; }
                #pragma unroll
                for (int off = 8; off; off >>= 1) {
                    s += __shfl_xor_sync(0xffffffffu, s, off);
                    q += __shfl_xor_sync(0xffffffffu, q, off);
                }
                if ((lane & 15) == 0) {
                    int gi = b*8 + octile*2 + (lane >> 4);
                    atomicAdd(&g_sum_t[gi], s);
                    atomicAdd(&g_ssq_t[gi], q);
                }
            } else {
                const float* sp = &g_s[cs][b][oc][0][0] + goff;
                float4 s1 = *(const float4*)sp;
                float4 s2 = *(const float4*)(sp + 4);
                float gc = sB2[oc], gh = sB3[oc];
                float4 o1, o2;
                o1.x = vals[0] + fmaf(s1.x, gc, gh);
                o1.y = vals[1] + fmaf(s1.y, gc, gh);
                o1.z = vals[2] + fmaf(s1.z, gc, gh);
                o1.w = vals[3] + fmaf(s1.w, gc, gh);
                o2.x = vals[4] + fmaf(s2.x, gc, gh);
                o2.y = vals[5] + fmaf(s2.y, gc, gh);
                o2.z = vals[6] + fmaf(s2.z, gc, gh);
                o2.w = vals[7] + fmaf(s2.w, gc, gh);
                float* op = Out + ((size_t)(cs*BB + b)*CC + oc)*NPIX + goff;
                *(float4*)op       = o1;
                *(float4*)(op + 4) = o2;
            }
        }
        __syncthreads();
    }
}

// ---------------- launch ----------------
extern "C" void kernel_launch(void* const* d_in, const int* in_sizes, int n_in,
                              void* d_out, int out_size) {
    const float* x0      = (const float*)d_in[0];
    const float* x1      = (const float*)d_in[1];
    const float* g1      = (const float*)d_in[2];
    const float* b1      = (const float*)d_in[3];
    const float* w1c     = (const float*)d_in[4];
    const float* w1k     = (const float*)d_in[5];
    const float* bias1   = (const float*)d_in[6];
    const float* g2      = (const float*)d_in[7];
    const float* b2      = (const float*)d_in[8];
    const float* w2c     = (const float*)d_in[9];
    const float* w2k     = (const float*)d_in[10];
    const float* bias2   = (const float*)d_in[11];
    const float* wskip   = (const float*)d_in[12];
    const float* bskip   = (const float*)d_in[13];
    const float* gskip   = (const float*)d_in[14];
    const float* betask  = (const float*)d_in[15];

    cudaFuncSetAttribute(conv_w_k<1>, cudaFuncAttributeMaxDynamicSharedMemorySize, W_TOTAL);
    cudaFuncSetAttribute(conv_w_k<2>, cudaFuncAttributeMaxDynamicSharedMemorySize, W_TOTAL);

    zero_stats_k<<<1, 128>>>();
    prep_w_k<<<160, 256>>>(w1c, w1k, w2c, w2k);
    skip_k<<<dim3(16, 32, 8), 256>>>(x0, x1, wskip, bskip);
    finalize1_k<<<1, 32>>>();

    dim3 grid(2, 32, 4);   // z = b + 2*cs
    conv_w_k<1><<<grid, 512, W_TOTAL>>>(x0, x1, bias1, g1, b1,
                                        nullptr, nullptr, nullptr);
    finalize2_k<<<1, 64>>>();
    conv_w_k<2><<<grid, 512, W_TOTAL>>>(nullptr, nullptr, bias2, g2, b2,
                                        gskip, betask, (float*)d_out);
    (void)in_sizes; (void)n_in; (void)out_size;
}

// round 16
// speedup vs baseline: 3.0837x; 1.0376x over previous
#include <cuda_runtime.h>
#include <cuda_fp16.h>
#include <mma.h>
#include <cstdint>
using namespace nvcuda;

#define HH 256
#define WW 256
#define BB 2
#define CC 64
#define EPSV 1e-5f
#define NPIX (HH*WW)
#define NGRP 16
#define NELEM_GRP (8*NPIX*2)
#define YB 8

// ---------------- scratch ----------------
__device__ float g_t[2][BB][CC][HH][WW];
__device__ float g_s[2][BB][CC][HH][WW];
__device__ float g_sum_x[NGRP], g_ssq_x[NGRP];
__device__ float g_sum_t[NGRP], g_ssq_t[NGRP];
__device__ float g_sum_s[NGRP], g_ssq_s[NGRP];
__device__ float g_mean1[NGRP], g_inv1[NGRP];
__device__ float g_mean2[NGRP], g_inv2[NGRP];
__device__ float g_means[NGRP], g_invs[NGRP];
// fp16 weights: hi exact-rounded, lo = (w - hi) * 1024 (subnormal-safe)
// pass1: 6 views {c,k00,k01,k10,k11,skip}; pass2: 5 views
__device__ __half g_w1h[6*4096], g_w1l[6*4096];
__device__ __half g_w2h[5*4096], g_w2l[5*4096];

__device__ __forceinline__ uint32_t smem_u32(const void* p) {
    uint32_t a;
    asm("{ .reg .u64 t; cvta.to.shared.u64 t, %1; cvt.u32.u64 %0, t; }" : "=r"(a) : "l"(p));
    return a;
}
#define CP16(dst, src) asm volatile("cp.async.ca.shared.global [%0], [%1], 16;" :: "r"(dst), "l"(src))
#define CP_COMMIT() asm volatile("cp.async.commit_group;")
#define CP_WAIT0()  asm volatile("cp.async.wait_group 0;" ::: "memory")

// ---------------- small kernels ----------------
__global__ void zero_stats_k() {
    int i = threadIdx.x;
    if (i < NGRP) {
        g_sum_x[i] = 0.f; g_ssq_x[i] = 0.f;
        g_sum_t[i] = 0.f; g_ssq_t[i] = 0.f;
        g_sum_s[i] = 0.f; g_ssq_s[i] = 0.f;
    }
}

__global__ void prep_w_k(const float* __restrict__ w1c, const float* __restrict__ w1k,
                         const float* __restrict__ ws,
                         const float* __restrict__ w2c, const float* __restrict__ w2k) {
    int idx = blockIdx.x * 256 + threadIdx.x;
    const int P1 = 6*4096;
    if (idx >= P1 + 5*4096) return;
    float w;
    if (idx < P1) {
        int v = idx >> 12, oi = idx & 4095;
        w = (v == 0) ? w1c[oi] : (v <= 4 ? w1k[oi*4 + (v-1)] : ws[oi]);
        __half hi = __float2half(w);
        __half lo = __float2half((w - __half2float(hi)) * 1024.f);
        g_w1h[idx] = hi; g_w1l[idx] = lo;
    } else {
        int rem = idx - P1;
        int v = rem >> 12, oi = rem & 4095;
        w = (v == 0) ? w2c[oi] : w2k[oi*4 + (v-1)];
        __half hi = __float2half(w);
        __half lo = __float2half((w - __half2float(hi)) * 1024.f);
        g_w2h[rem] = hi; g_w2l[rem] = lo;
    }
}

__global__ void stats_x_k(const float* __restrict__ x0, const float* __restrict__ x1) {
    int slab = blockIdx.y;
    int cs = slab >> 4, b = (slab >> 3) & 1, g = slab & 7;
    const float* src = (cs ? x1 : x0) + ((size_t)(b*CC + g*8)) * NPIX
                       + (size_t)blockIdx.x * 16384;
    const float4* p = (const float4*)src;
    float s = 0.f, ss = 0.f;
    for (int i = threadIdx.x; i < 4096; i += 256) {
        float4 v = p[i];
        s  += (v.x + v.y) + (v.z + v.w);
        ss += (v.x*v.x + v.y*v.y) + (v.z*v.z + v.w*v.w);
    }
    __shared__ float sh[256], sh2[256];
    sh[threadIdx.x] = s; sh2[threadIdx.x] = ss;
    __syncthreads();
    for (int o = 128; o > 0; o >>= 1) {
        if (threadIdx.x < o) { sh[threadIdx.x] += sh[threadIdx.x+o]; sh2[threadIdx.x] += sh2[threadIdx.x+o]; }
        __syncthreads();
    }
    if (threadIdx.x == 0) {
        atomicAdd(&g_sum_x[b*8+g], sh[0]);
        atomicAdd(&g_ssq_x[b*8+g], sh2[0]);
    }
}

__global__ void finalize1_k() {
    int i = threadIdx.x;
    if (i < NGRP) {
        float n = (float)NELEM_GRP;
        float m = g_sum_x[i] / n;
        float v = g_ssq_x[i] / n - m*m;
        g_mean1[i] = m; g_inv1[i] = rsqrtf(v + EPSV);
    }
}

__global__ void finalize2_k() {
    int i = threadIdx.x;
    float n = (float)NELEM_GRP;
    if (i < NGRP) {
        float m = g_sum_t[i] / n;
        float v = g_ssq_t[i] / n - m*m;
        g_mean2[i] = m; g_inv2[i] = rsqrtf(v + EPSV);
    } else if (i < 2*NGRP) {
        int j = i - NGRP;
        float m = g_sum_s[j] / n;
        float v = g_ssq_s[j] / n - m*m;
        g_means[j] = m; g_invs[j] = rsqrtf(v + EPSV);
    }
}

// ---------------- wmma conv kernel (fp16, fused skip in pass 1) ----------------
// grid (2, 32, 4); 512 thr = 16 warps; warp = octile(>>2) x pxquad(&3).
#define ROWB     272
#define W_MISC   0
#define W_WH     1280                      // 6*8192 = 49152
#define W_WL     50432                     // 49152
#define W_CEN    99584                     // 17408
#define W_RAW    116992                    // 17408 (pass1 raw x fp16)
#define W_CRS    134400                    // 2 slots * 2 shifts * 17408 = 69632
#define W_CST    204032                    // 16 warps * 1280
#define W_TOTAL  224512
#define CRS_SLOT 34816
#define CRS_SHFT 17408
#define LO_SCL   (1.f/1024.f)

template<int PASS>
__global__ __launch_bounds__(512, 1)
void conv_w_k(const float* __restrict__ in0, const float* __restrict__ in1,
              const float* __restrict__ Bi,
              const float* __restrict__ Ga, const float* __restrict__ Be,
              const float* __restrict__ SkB,
              const float* __restrict__ Gs, const float* __restrict__ BeS,
              float* __restrict__ Out)
{
    constexpr int NMAT = (PASS == 1) ? 6 : 5;
    extern __shared__ __align__(128) char smraw[];
    float* sScale = (float*)(smraw + W_MISC);
    float* sShift = sScale + 64;
    float* sBias  = sShift + 64;
    float* sB2    = sBias + 64;    // pass1: skip bias; pass2: skip-GN scale
    float* sB3    = sB2 + 64;      // pass2: skip-GN shift

    int tid = threadIdx.x, warp = tid >> 5, lane = tid & 31;
    int bc = blockIdx.z; int b = bc & 1, cs = bc >> 1;
    int y0 = blockIdx.y * YB;
    int x0 = blockIdx.x * 128;

    const float* same_base;
    const float* cross_base;
    if (PASS == 1) {
        same_base  = (cs ? in1 : in0) + (size_t)b * CC * NPIX;
        cross_base = (cs ? in0 : in1) + (size_t)b * CC * NPIX;
    } else {
        same_base  = &g_t[cs][b][0][0][0];
        cross_base = &g_t[cs ^ 1][b][0][0][0];
    }
    const float* meanA = (PASS == 1) ? g_mean1 : g_mean2;
    const float* invA  = (PASS == 1) ? g_inv1  : g_inv2;

    // weights cp.async
    {
        uint32_t sb = smem_u32(smraw);
        const char* hsrc = (const char*)((PASS == 1) ? g_w1h : g_w2h);
        const char* lsrc = (const char*)((PASS == 1) ? g_w1l : g_w2l);
        for (int i = tid; i < NMAT*512; i += 512) {
            CP16(sb + W_WH + i*16, hsrc + (size_t)i*16);
            CP16(sb + W_WL + i*16, lsrc + (size_t)i*16);
        }
        CP_COMMIT();
    }
    if (tid < 64) {
        int grp = tid >> 3;
        float m = meanA[b*8+grp], iv = invA[b*8+grp];
        float sc = iv * Ga[tid];
        sScale[tid] = sc;
        sShift[tid] = Be[tid] - m * sc;
        sBias[tid]  = Bi[tid];
        if (PASS == 1) {
            sB2[tid] = SkB[tid];
        } else {
            float ivs = g_invs[b*8+grp];
            float gsc = Gs[tid] * ivs;
            sB2[tid] = gsc;
            sB3[tid] = BeS[tid] - g_means[b*8+grp] * gsc;
        }
    }
    __syncthreads();

    wmma::fragment<wmma::matrix_a, 16, 16, 16, __half, wmma::row_major> aH, aL;
    wmma::fragment<wmma::matrix_b, 16, 16, 16, __half, wmma::row_major> b0, b1;
    wmma::fragment<wmma::accumulator, 16, 16, 16, float> cH0, cH1, cL0, cL1;
    float* cst = (float*)(smraw + W_CST + warp*1280);

    int gx0 = x0 + cs - 1;

    // stage one cross row into (slot, shift) buffers
    auto stage_cross = [&](int yy) {
        int slot = yy & 1;
        char* d0 = smraw + W_CRS + slot*CRS_SLOT;
        char* d1 = d0 + CRS_SHFT;
        bool yok = ((unsigned)yy < HH);
        #pragma unroll
        for (int k = 0; k < 4; ++k) {
            int ic = warp*4 + k;
            float sc = sScale[ic], sf = sShift[ic];
            const float* srow = cross_base + (size_t)ic*NPIX + (size_t)(yok ? yy : 0)*WW;
            #pragma unroll
            for (int m = 0; m < 5; ++m) {
                int j = lane + m*32;
                float v = 0.f;
                int gx = gx0 + j;
                if (yok && j < 130 && (unsigned)gx < WW)
                    v = fmaxf(fmaf(__ldg(srow + gx), sc, sf), 0.f);
                __half hv = __float2half(v);
                if (j < 136)           *(__half*)(d0 + ic*ROWB + j*2)     = hv;
                if (j >= 1 && j < 137) *(__half*)(d1 + ic*ROWB + (j-1)*2) = hv;
            }
        }
    };

    stage_cross(y0 + cs - 1);
    stage_cross(y0 + cs);
    CP_WAIT0();

    for (int i = 0; i < YB; ++i) {
        int y = y0 + i;
        // center staging (and raw x for skip in pass 1)
        #pragma unroll
        for (int k = 0; k < 4; ++k) {
            int ic = warp*4 + k;
            float sc = sScale[ic], sf = sShift[ic];
            float4 v4 = *(const float4*)(same_base + (size_t)ic*NPIX + (size_t)y*WW + x0 + lane*4);
            __half2 h0 = __floats2half2_rn(fmaxf(fmaf(v4.x, sc, sf), 0.f),
                                           fmaxf(fmaf(v4.y, sc, sf), 0.f));
            __half2 h1 = __floats2half2_rn(fmaxf(fmaf(v4.z, sc, sf), 0.f),
                                           fmaxf(fmaf(v4.w, sc, sf), 0.f));
            uint32_t u0 = *(uint32_t*)&h0, u1 = *(uint32_t*)&h1;
            *(uint2*)(smraw + W_CEN + ic*ROWB + lane*8) = make_uint2(u0, u1);
            if (PASS == 1) {
                __half2 r0 = __floats2half2_rn(v4.x, v4.y);
                __half2 r1 = __floats2half2_rn(v4.z, v4.w);
                uint32_t w0 = *(uint32_t*)&r0, w1 = *(uint32_t*)&r1;
                *(uint2*)(smraw + W_RAW + ic*ROWB + lane*8) = make_uint2(w0, w1);
            }
        }
        if (i > 0) stage_cross(y + cs);
        __syncthreads();

        int octile = warp >> 2;
        int px0 = (warp & 3) * 32;
        wmma::fill_fragment(cH0, 0.f); wmma::fill_fragment(cH1, 0.f);
        wmma::fill_fragment(cL0, 0.f); wmma::fill_fragment(cL1, 0.f);

        #pragma unroll
        for (int v = 0; v < 5; ++v) {
            const char* bb;
            if (v == 0) {
                bb = smraw + W_CEN;
            } else {
                int dy = (v-1) >> 1, dx = (v-1) & 1;
                int slot = (y + cs - 1 + dy) & 1;
                bb = smraw + W_CRS + slot*CRS_SLOT + dx*CRS_SHFT;
            }
            const char* whb = smraw + W_WH + v*8192;
            const char* wlb = smraw + W_WL + v*8192;
            #pragma unroll
            for (int kc = 0; kc < 4; ++kc) {
                wmma::load_matrix_sync(aH, (const __half*)(whb + octile*2048 + kc*32), 64);
                wmma::load_matrix_sync(aL, (const __half*)(wlb + octile*2048 + kc*32), 64);
                wmma::load_matrix_sync(b0, (const __half*)(bb + kc*16*ROWB + px0*2), 136);
                wmma::load_matrix_sync(b1, (const __half*)(bb + kc*16*ROWB + (px0+16)*2), 136);
                wmma::mma_sync(cH0, aH, b0, cH0);
                wmma::mma_sync(cL0, aL, b0, cL0);
                wmma::mma_sync(cH1, aH, b1, cH1);
                wmma::mma_sync(cL1, aL, b1, cL1);
            }
        }
        #pragma unroll
        for (int e = 0; e < cH0.num_elements; ++e) {
            cH0.x[e] = fmaf(cL0.x[e], LO_SCL, cH0.x[e]);
            cH1.x[e] = fmaf(cL1.x[e], LO_SCL, cH1.x[e]);
        }

        // conv epilogue
        #pragma unroll
        for (int t = 0; t < 2; ++t) {
            __syncwarp();
            wmma::store_matrix_sync(cst, (t == 0) ? cH0 : cH1, 20, wmma::mem_row_major);
            __syncwarp();

            int r0 = lane >> 1, cb8 = (lane & 1) * 8;
            int oc = octile*16 + r0;
            int pxb = px0 + t*16 + cb8;
            float bv = sBias[oc];
            float vals[8];
            #pragma unroll
            for (int j = 0; j < 8; ++j) vals[j] = cst[r0*20 + cb8 + j] + bv;

            size_t goff = (size_t)y * WW + x0 + pxb;
            if (PASS == 1) {
                float* tp = &g_t[cs][b][oc][0][0] + goff;
                *(float4*)tp       = make_float4(vals[0], vals[1], vals[2], vals[3]);
                *(float4*)(tp + 4) = make_float4(vals[4], vals[5], vals[6], vals[7]);
                float s = 0.f, q = 0.f;
                #pragma unroll
                for (int j = 0; j < 8; ++j) { s += vals[j]; q += vals[j]*vals[j]; }
                #pragma unroll
                for (int off = 8; off; off >>= 1) {
                    s += __shfl_xor_sync(0xffffffffu, s, off);
                    q += __shfl_xor_sync(0xffffffffu, q, off);
                }
                if ((lane & 15) == 0) {
                    int gi = b*8 + octile*2 + (lane >> 4);
                    atomicAdd(&g_sum_t[gi], s);
                    atomicAdd(&g_ssq_t[gi], q);
                }
            } else {
                const float* sp = &g_s[cs][b][oc][0][0] + goff;
                float4 s1 = *(const float4*)sp;
                float4 s2 = *(const float4*)(sp + 4);
                float gc = sB2[oc], gh = sB3[oc];
                float4 o1, o2;
                o1.x = vals[0] + fmaf(s1.x, gc, gh);
                o1.y = vals[1] + fmaf(s1.y, gc, gh);
                o1.z = vals[2] + fmaf(s1.z, gc, gh);
                o1.w = vals[3] + fmaf(s1.w, gc, gh);
                o2.x = vals[4] + fmaf(s2.x, gc, gh);
                o2.y = vals[5] + fmaf(s2.y, gc, gh);
                o2.z = vals[6] + fmaf(s2.z, gc, gh);
                o2.w = vals[7] + fmaf(s2.w, gc, gh);
                float* op = Out + ((size_t)(cs*BB + b)*CC + oc)*NPIX + goff;
                *(float4*)op       = o1;
                *(float4*)(op + 4) = o2;
            }
        }

        // skip view (pass 1 only): s = Ws * raw_x + bs -> g_s + s-stats
        if (PASS == 1) {
            wmma::fragment<wmma::accumulator, 16, 16, 16, float> cS0, cS1;
            wmma::fill_fragment(cS0, 0.f);
            wmma::fill_fragment(cS1, 0.f);
            const char* whb = smraw + W_WH + 5*8192;
            const char* bb  = smraw + W_RAW;
            #pragma unroll
            for (int kc = 0; kc < 4; ++kc) {
                wmma::load_matrix_sync(aH, (const __half*)(whb + octile*2048 + kc*32), 64);
                wmma::load_matrix_sync(b0, (const __half*)(bb + kc*16*ROWB + px0*2), 136);
                wmma::load_matrix_sync(b1, (const __half*)(bb + kc*16*ROWB + (px0+16)*2), 136);
                wmma::mma_sync(cS0, aH, b0, cS0);
                wmma::mma_sync(cS1, aH, b1, cS1);
            }
            #pragma unroll
            for (int t = 0; t < 2; ++t) {
                __syncwarp();
                wmma::store_matrix_sync(cst, (t == 0) ? cS0 : cS1, 20, wmma::mem_row_major);
                __syncwarp();

                int r0 = lane >> 1, cb8 = (lane & 1) * 8;
                int oc = octile*16 + r0;
                int pxb = px0 + t*16 + cb8;
                float bv = sB2[oc];
                float vals[8];
                #pragma unroll
                for (int j = 0; j < 8; ++j) vals[j] = cst[r0*20 + cb8 + j] + bv;

                size_t goff = (size_t)y * WW + x0 + pxb;
                float* sp = &g_s[cs][b][oc][0][0] + goff;
                *(float4*)sp       = make_float4(vals[0], vals[1], vals[2], vals[3]);
                *(float4*)(sp + 4) = make_float4(vals[4], vals[5], vals[6], vals[7]);
                float s = 0.f, q = 0.f;
                #pragma unroll
                for (int j = 0; j < 8; ++j) { s += vals[j]; q += vals[j]*vals[j]; }
                #pragma unroll
                for (int off = 8; off; off >>= 1) {
                    s += __shfl_xor_sync(0xffffffffu, s, off);
                    q += __shfl_xor_sync(0xffffffffu, q, off);
                }
                if ((lane & 15) == 0) {
                    int gi = b*8 + octile*2 + (lane >> 4);
                    atomicAdd(&g_sum_s[gi], s);
                    atomicAdd(&g_ssq_s[gi], q);
                }
            }
        }
        __syncthreads();
    }
}

// ---------------- launch ----------------
extern "C" void kernel_launch(void* const* d_in, const int* in_sizes, int n_in,
                              void* d_out, int out_size) {
    const float* x0      = (const float*)d_in[0];
    const float* x1      = (const float*)d_in[1];
    const float* g1      = (const float*)d_in[2];
    const float* b1      = (const float*)d_in[3];
    const float* w1c     = (const float*)d_in[4];
    const float* w1k     = (const float*)d_in[5];
    const float* bias1   = (const float*)d_in[6];
    const float* g2      = (const float*)d_in[7];
    const float* b2      = (const float*)d_in[8];
    const float* w2c     = (const float*)d_in[9];
    const float* w2k     = (const float*)d_in[10];
    const float* bias2   = (const float*)d_in[11];
    const float* wskip   = (const float*)d_in[12];
    const float* bskip   = (const float*)d_in[13];
    const float* gskip   = (const float*)d_in[14];
    const float* betask  = (const float*)d_in[15];

    cudaFuncSetAttribute(conv_w_k<1>, cudaFuncAttributeMaxDynamicSharedMemorySize, W_TOTAL);
    cudaFuncSetAttribute(conv_w_k<2>, cudaFuncAttributeMaxDynamicSharedMemorySize, W_TOTAL);

    zero_stats_k<<<1, 128>>>();
    prep_w_k<<<176, 256>>>(w1c, w1k, wskip, w2c, w2k);
    stats_x_k<<<dim3(32, 32), 256>>>(x0, x1);
    finalize1_k<<<1, 32>>>();

    dim3 grid(2, 32, 4);   // z = b + 2*cs
    conv_w_k<1><<<grid, 512, W_TOTAL>>>(x0, x1, bias1, g1, b1,
                                        bskip, nullptr, nullptr, nullptr);
    finalize2_k<<<1, 64>>>();
    conv_w_k<2><<<grid, 512, W_TOTAL>>>(nullptr, nullptr, bias2, g2, b2,
                                        nullptr, gskip, betask, (float*)d_out);
    (void)in_sizes; (void)n_in; (void)out_size;
}

// round 17
// speedup vs baseline: 3.3235x; 1.0778x over previous
#include <cuda_runtime.h>
#include <cuda_fp16.h>
#include <mma.h>
#include <cstdint>
using namespace nvcuda;

#define HH 256
#define WW 256
#define BB 2
#define CC 64
#define EPSV 1e-5f
#define NPIX (HH*WW)
#define NGRP 16
#define NELEM_GRP (8*NPIX*2)
#define YB 8

// ---------------- scratch ----------------
__device__ float g_t[2][BB][CC][HH][WW];
__device__ float g_s[2][BB][CC][HH][WW];
__device__ float g_sum_x[NGRP], g_ssq_x[NGRP];
__device__ float g_sum_t[NGRP], g_ssq_t[NGRP];
__device__ float g_sum_s[NGRP], g_ssq_s[NGRP];
__device__ float g_mean1[NGRP], g_inv1[NGRP];
__device__ float g_mean2[NGRP], g_inv2[NGRP];
__device__ float g_means[NGRP], g_invs[NGRP];
// fp16 weights: hi exact-rounded, lo = (w - hi) * 1024
__device__ __half g_w1h[6*4096], g_w1l[6*4096];
__device__ __half g_w2h[5*4096], g_w2l[5*4096];

__device__ __forceinline__ uint32_t smem_u32(const void* p) {
    uint32_t a;
    asm("{ .reg .u64 t; cvta.to.shared.u64 t, %1; cvt.u32.u64 %0, t; }" : "=r"(a) : "l"(p));
    return a;
}
#define CP16(dst, src) asm volatile("cp.async.ca.shared.global [%0], [%1], 16;" :: "r"(dst), "l"(src))
#define CP_COMMIT() asm volatile("cp.async.commit_group;")
#define CP_WAIT0()  asm volatile("cp.async.wait_group 0;" ::: "memory")

// ---------------- small kernels ----------------
__global__ void zero_stats_k() {
    int i = threadIdx.x;
    if (i < NGRP) {
        g_sum_x[i] = 0.f; g_ssq_x[i] = 0.f;
        g_sum_t[i] = 0.f; g_ssq_t[i] = 0.f;
        g_sum_s[i] = 0.f; g_ssq_s[i] = 0.f;
    }
}

__global__ void prep_w_k(const float* __restrict__ w1c, const float* __restrict__ w1k,
                         const float* __restrict__ ws,
                         const float* __restrict__ w2c, const float* __restrict__ w2k) {
    int idx = blockIdx.x * 256 + threadIdx.x;
    const int P1 = 6*4096;
    if (idx >= P1 + 5*4096) return;
    float w;
    if (idx < P1) {
        int v = idx >> 12, oi = idx & 4095;
        w = (v == 0) ? w1c[oi] : (v <= 4 ? w1k[oi*4 + (v-1)] : ws[oi]);
        __half hi = __float2half(w);
        __half lo = __float2half((w - __half2float(hi)) * 1024.f);
        g_w1h[idx] = hi; g_w1l[idx] = lo;
    } else {
        int rem = idx - P1;
        int v = rem >> 12, oi = rem & 4095;
        w = (v == 0) ? w2c[oi] : w2k[oi*4 + (v-1)];
        __half hi = __float2half(w);
        __half lo = __float2half((w - __half2float(hi)) * 1024.f);
        g_w2h[rem] = hi; g_w2l[rem] = lo;
    }
}

__global__ void stats_x_k(const float* __restrict__ x0, const float* __restrict__ x1) {
    int slab = blockIdx.y;
    int cs = slab >> 4, b = (slab >> 3) & 1, g = slab & 7;
    const float* src = (cs ? x1 : x0) + ((size_t)(b*CC + g*8)) * NPIX
                       + (size_t)blockIdx.x * 16384;
    const float4* p = (const float4*)src;
    float s = 0.f, ss = 0.f;
    for (int i = threadIdx.x; i < 4096; i += 256) {
        float4 v = p[i];
        s  += (v.x + v.y) + (v.z + v.w);
        ss += (v.x*v.x + v.y*v.y) + (v.z*v.z + v.w*v.w);
    }
    __shared__ float sh[256], sh2[256];
    sh[threadIdx.x] = s; sh2[threadIdx.x] = ss;
    __syncthreads();
    for (int o = 128; o > 0; o >>= 1) {
        if (threadIdx.x < o) { sh[threadIdx.x] += sh[threadIdx.x+o]; sh2[threadIdx.x] += sh2[threadIdx.x+o]; }
        __syncthreads();
    }
    if (threadIdx.x == 0) {
        atomicAdd(&g_sum_x[b*8+g], sh[0]);
        atomicAdd(&g_ssq_x[b*8+g], sh2[0]);
    }
}

__global__ void finalize1_k() {
    int i = threadIdx.x;
    if (i < NGRP) {
        float n = (float)NELEM_GRP;
        float m = g_sum_x[i] / n;
        float v = g_ssq_x[i] / n - m*m;
        g_mean1[i] = m; g_inv1[i] = rsqrtf(v + EPSV);
    }
}

__global__ void finalize2_k() {
    int i = threadIdx.x;
    float n = (float)NELEM_GRP;
    if (i < NGRP) {
        float m = g_sum_t[i] / n;
        float v = g_ssq_t[i] / n - m*m;
        g_mean2[i] = m; g_inv2[i] = rsqrtf(v + EPSV);
    } else if (i < 2*NGRP) {
        int j = i - NGRP;
        float m = g_sum_s[j] / n;
        float v = g_ssq_s[j] / n - m*m;
        g_means[j] = m; g_invs[j] = rsqrtf(v + EPSV);
    }
}

// ---------------- wmma conv kernel (fp16, fused skip, prefetch-pipelined) ----------------
#define ROWB     272
#define W_MISC   0
#define W_WH     1280
#define W_WL     50432
#define W_CEN    99584
#define W_RAW    116992
#define W_CRS    134400
#define W_CST    204032
#define W_TOTAL  224512
#define CRS_SLOT 34816
#define CRS_SHFT 17408
#define LO_SCL   (1.f/1024.f)

template<int PASS>
__global__ __launch_bounds__(512, 1)
void conv_w_k(const float* __restrict__ in0, const float* __restrict__ in1,
              const float* __restrict__ Bi,
              const float* __restrict__ Ga, const float* __restrict__ Be,
              const float* __restrict__ SkB,
              const float* __restrict__ Gs, const float* __restrict__ BeS,
              float* __restrict__ Out)
{
    constexpr int NMAT = (PASS == 1) ? 6 : 5;
    extern __shared__ __align__(128) char smraw[];
    float* sScale = (float*)(smraw + W_MISC);
    float* sShift = sScale + 64;
    float* sBias  = sShift + 64;
    float* sB2    = sBias + 64;
    float* sB3    = sB2 + 64;

    int tid = threadIdx.x, warp = tid >> 5, lane = tid & 31;
    int bc = blockIdx.z; int b = bc & 1, cs = bc >> 1;
    int y0 = blockIdx.y * YB;
    int x0 = blockIdx.x * 128;

    const float* same_base;
    const float* cross_base;
    if (PASS == 1) {
        same_base  = (cs ? in1 : in0) + (size_t)b * CC * NPIX;
        cross_base = (cs ? in0 : in1) + (size_t)b * CC * NPIX;
    } else {
        same_base  = &g_t[cs][b][0][0][0];
        cross_base = &g_t[cs ^ 1][b][0][0][0];
    }
    const float* meanA = (PASS == 1) ? g_mean1 : g_mean2;
    const float* invA  = (PASS == 1) ? g_inv1  : g_inv2;

    // weights cp.async
    {
        uint32_t sb = smem_u32(smraw);
        const char* hsrc = (const char*)((PASS == 1) ? g_w1h : g_w2h);
        const char* lsrc = (const char*)((PASS == 1) ? g_w1l : g_w2l);
        for (int i = tid; i < NMAT*512; i += 512) {
            CP16(sb + W_WH + i*16, hsrc + (size_t)i*16);
            CP16(sb + W_WL + i*16, lsrc + (size_t)i*16);
        }
        CP_COMMIT();
    }
    if (tid < 64) {
        int grp = tid >> 3;
        float m = meanA[b*8+grp], iv = invA[b*8+grp];
        float sc = iv * Ga[tid];
        sScale[tid] = sc;
        sShift[tid] = Be[tid] - m * sc;
        sBias[tid]  = Bi[tid];
        if (PASS == 1) {
            sB2[tid] = SkB[tid];
        } else {
            float ivs = g_invs[b*8+grp];
            float gsc = Gs[tid] * ivs;
            sB2[tid] = gsc;
            sB3[tid] = BeS[tid] - g_means[b*8+grp] * gsc;
        }
    }
    __syncthreads();

    wmma::fragment<wmma::matrix_a, 16, 16, 16, __half, wmma::row_major> aH, aL;
    wmma::fragment<wmma::matrix_b, 16, 16, 16, __half, wmma::row_major> b0, b1;
    wmma::fragment<wmma::accumulator, 16, 16, 16, float> cH0, cH1, cL0, cL1;
    float* cst = (float*)(smraw + W_CST + warp*1280);

    int gx0 = x0 + cs - 1;
    int ic0 = warp * 4;
    float scv[4], sfv[4];
    #pragma unroll
    for (int k = 0; k < 4; ++k) { scv[k] = sScale[ic0+k]; sfv[k] = sShift[ic0+k]; }

    // ---- prefetch helpers (regs) ----
    // cross raw: [k][m], j = lane + m*32 (20 floats)
    auto load_cross_regs = [&](int yy, float* dst) {
        bool yok = ((unsigned)yy < HH);
        #pragma unroll
        for (int k = 0; k < 4; ++k) {
            const float* srow = cross_base + (size_t)(ic0+k)*NPIX + (size_t)(yok ? yy : 0)*WW;
            #pragma unroll
            for (int m = 0; m < 5; ++m) {
                int j = lane + m*32;
                int gx = gx0 + j;
                float v = 0.f;
                if (yok && j < 130 && (unsigned)gx < WW) v = __ldg(srow + gx);
                dst[k*5+m] = v;
            }
        }
    };
    // normalize + STS cross row from regs (predicate recomputed so OOB stays exact 0)
    auto sts_cross = [&](int yy, const float* src) {
        int slot = yy & 1;
        char* d0 = smraw + W_CRS + slot*CRS_SLOT;
        char* d1 = d0 + CRS_SHFT;
        bool yok = ((unsigned)yy < HH);
        #pragma unroll
        for (int k = 0; k < 4; ++k) {
            int ic = ic0 + k;
            #pragma unroll
            for (int m = 0; m < 5; ++m) {
                int j = lane + m*32;
                int gx = gx0 + j;
                bool ok = yok && j < 130 && (unsigned)gx < WW;
                float v = ok ? fmaxf(fmaf(src[k*5+m], scv[k], sfv[k]), 0.f) : 0.f;
                __half hv = __float2half(v);
                if (j < 136)           *(__half*)(d0 + ic*ROWB + j*2)     = hv;
                if (j >= 1 && j < 137) *(__half*)(d1 + ic*ROWB + (j-1)*2) = hv;
            }
        }
    };

    float crsReg[20];
    float4 cenReg[4];

    // prologue: stage both initial cross rows directly; prefetch center row 0
    load_cross_regs(y0 + cs - 1, crsReg);
    sts_cross(y0 + cs - 1, crsReg);
    load_cross_regs(y0 + cs, crsReg);
    sts_cross(y0 + cs, crsReg);
    #pragma unroll
    for (int k = 0; k < 4; ++k)
        cenReg[k] = *(const float4*)(same_base + (size_t)(ic0+k)*NPIX + (size_t)y0*WW + x0 + lane*4);
    load_cross_regs(y0 + 1 + cs, crsReg);   // cross row for iter 1
    CP_WAIT0();

    for (int i = 0; i < YB; ++i) {
        int y = y0 + i;
        // center STS from prefetched regs (+ raw for skip in pass 1)
        #pragma unroll
        for (int k = 0; k < 4; ++k) {
            int ic = ic0 + k;
            float4 v4 = cenReg[k];
            __half2 h0 = __floats2half2_rn(fmaxf(fmaf(v4.x, scv[k], sfv[k]), 0.f),
                                           fmaxf(fmaf(v4.y, scv[k], sfv[k]), 0.f));
            __half2 h1 = __floats2half2_rn(fmaxf(fmaf(v4.z, scv[k], sfv[k]), 0.f),
                                           fmaxf(fmaf(v4.w, scv[k], sfv[k]), 0.f));
            uint32_t u0 = *(uint32_t*)&h0, u1 = *(uint32_t*)&h1;
            *(uint2*)(smraw + W_CEN + ic*ROWB + lane*8) = make_uint2(u0, u1);
            if (PASS == 1) {
                __half2 r0 = __floats2half2_rn(v4.x, v4.y);
                __half2 r1 = __floats2half2_rn(v4.z, v4.w);
                uint32_t w0 = *(uint32_t*)&r0, w1 = *(uint32_t*)&r1;
                *(uint2*)(smraw + W_RAW + ic*ROWB + lane*8) = make_uint2(w0, w1);
            }
        }
        // cross STS from prefetched regs (row y+cs, needed by this iter's dy=1)
        if (i > 0) sts_cross(y + cs, crsReg);

        // prefetch next iter's data BEFORE the barrier (overlaps with compute)
        if (i < YB - 1) {
            #pragma unroll
            for (int k = 0; k < 4; ++k)
                cenReg[k] = *(const float4*)(same_base + (size_t)(ic0+k)*NPIX
                                             + (size_t)(y+1)*WW + x0 + lane*4);
            load_cross_regs(y + 1 + cs, crsReg);
        }
        __syncthreads();

        int octile = warp >> 2;
        int px0 = (warp & 3) * 32;
        wmma::fill_fragment(cH0, 0.f); wmma::fill_fragment(cH1, 0.f);
        wmma::fill_fragment(cL0, 0.f); wmma::fill_fragment(cL1, 0.f);

        #pragma unroll
        for (int v = 0; v < 5; ++v) {
            const char* bb;
            if (v == 0) {
                bb = smraw + W_CEN;
            } else {
                int dy = (v-1) >> 1, dx = (v-1) & 1;
                int slot = (y + cs - 1 + dy) & 1;
                bb = smraw + W_CRS + slot*CRS_SLOT + dx*CRS_SHFT;
            }
            const char* whb = smraw + W_WH + v*8192;
            const char* wlb = smraw + W_WL + v*8192;
            #pragma unroll
            for (int kc = 0; kc < 4; ++kc) {
                wmma::load_matrix_sync(aH, (const __half*)(whb + octile*2048 + kc*32), 64);
                wmma::load_matrix_sync(aL, (const __half*)(wlb + octile*2048 + kc*32), 64);
                wmma::load_matrix_sync(b0, (const __half*)(bb + kc*16*ROWB + px0*2), 136);
                wmma::load_matrix_sync(b1, (const __half*)(bb + kc*16*ROWB + (px0+16)*2), 136);
                wmma::mma_sync(cH0, aH, b0, cH0);
                wmma::mma_sync(cL0, aL, b0, cL0);
                wmma::mma_sync(cH1, aH, b1, cH1);
                wmma::mma_sync(cL1, aL, b1, cL1);
            }
        }
        #pragma unroll
        for (int e = 0; e < cH0.num_elements; ++e) {
            cH0.x[e] = fmaf(cL0.x[e], LO_SCL, cH0.x[e]);
            cH1.x[e] = fmaf(cL1.x[e], LO_SCL, cH1.x[e]);
        }

        // conv epilogue
        #pragma unroll
        for (int t = 0; t < 2; ++t) {
            __syncwarp();
            wmma::store_matrix_sync(cst, (t == 0) ? cH0 : cH1, 20, wmma::mem_row_major);
            __syncwarp();

            int r0 = lane >> 1, cb8 = (lane & 1) * 8;
            int oc = octile*16 + r0;
            int pxb = px0 + t*16 + cb8;
            float bv = sBias[oc];
            float vals[8];
            #pragma unroll
            for (int j = 0; j < 8; ++j) vals[j] = cst[r0*20 + cb8 + j] + bv;

            size_t goff = (size_t)y * WW + x0 + pxb;
            if (PASS == 1) {
                float* tp = &g_t[cs][b][oc][0][0] + goff;
                *(float4*)tp       = make_float4(vals[0], vals[1], vals[2], vals[3]);
                *(float4*)(tp + 4) = make_float4(vals[4], vals[5], vals[6], vals[7]);
                float s = 0.f, q = 0.f;
                #pragma unroll
                for (int j = 0; j < 8; ++j) { s += vals[j]; q += vals[j]*vals[j]; }
                #pragma unroll
                for (int off = 8; off; off >>= 1) {
                    s += __shfl_xor_sync(0xffffffffu, s, off);
                    q += __shfl_xor_sync(0xffffffffu, q, off);
                }
                if ((lane & 15) == 0) {
                    int gi = b*8 + octile*2 + (lane >> 4);
                    atomicAdd(&g_sum_t[gi], s);
                    atomicAdd(&g_ssq_t[gi], q);
                }
            } else {
                const float* sp = &g_s[cs][b][oc][0][0] + goff;
                float4 s1 = *(const float4*)sp;
                float4 s2 = *(const float4*)(sp + 4);
                float gc = sB2[oc], gh = sB3[oc];
                float4 o1, o2;
                o1.x = vals[0] + fmaf(s1.x, gc, gh);
                o1.y = vals[1] + fmaf(s1.y, gc, gh);
                o1.z = vals[2] + fmaf(s1.z, gc, gh);
                o1.w = vals[3] + fmaf(s1.w, gc, gh);
                o2.x = vals[4] + fmaf(s2.x, gc, gh);
                o2.y = vals[5] + fmaf(s2.y, gc, gh);
                o2.z = vals[6] + fmaf(s2.z, gc, gh);
                o2.w = vals[7] + fmaf(s2.w, gc, gh);
                float* op = Out + ((size_t)(cs*BB + b)*CC + oc)*NPIX + goff;
                *(float4*)op       = o1;
                *(float4*)(op + 4) = o2;
            }
        }

        // skip view (pass 1 only)
        if (PASS == 1) {
            wmma::fragment<wmma::accumulator, 16, 16, 16, float> cS0, cS1;
            wmma::fill_fragment(cS0, 0.f);
            wmma::fill_fragment(cS1, 0.f);
            const char* whb = smraw + W_WH + 5*8192;
            const char* bb  = smraw + W_RAW;
            #pragma unroll
            for (int kc = 0; kc < 4; ++kc) {
                wmma::load_matrix_sync(aH, (const __half*)(whb + octile*2048 + kc*32), 64);
                wmma::load_matrix_sync(b0, (const __half*)(bb + kc*16*ROWB + px0*2), 136);
                wmma::load_matrix_sync(b1, (const __half*)(bb + kc*16*ROWB + (px0+16)*2), 136);
                wmma::mma_sync(cS0, aH, b0, cS0);
                wmma::mma_sync(cS1, aH, b1, cS1);
            }
            #pragma unroll
            for (int t = 0; t < 2; ++t) {
                __syncwarp();
                wmma::store_matrix_sync(cst, (t == 0) ? cS0 : cS1, 20, wmma::mem_row_major);
                __syncwarp();

                int r0 = lane >> 1, cb8 = (lane & 1) * 8;
                int oc = octile*16 + r0;
                int pxb = px0 + t*16 + cb8;
                float bv = sB2[oc];
                float vals[8];
                #pragma unroll
                for (int j = 0; j < 8; ++j) vals[j] = cst[r0*20 + cb8 + j] + bv;

                size_t goff = (size_t)y * WW + x0 + pxb;
                float* sp = &g_s[cs][b][oc][0][0] + goff;
                *(float4*)sp       = make_float4(vals[0], vals[1], vals[2], vals[3]);
                *(float4*)(sp + 4) = make_float4(vals[4], vals[5], vals[6], vals[7]);
                float s = 0.f, q = 0.f;
                #pragma unroll
                for (int j = 0; j < 8; ++j) { s += vals[j]; q += vals[j]*vals[j]; }
                #pragma unroll
                for (int off = 8; off; off >>= 1) {
                    s += __shfl_xor_sync(0xffffffffu, s, off);
                    q += __shfl_xor_sync(0xffffffffu, q, off);
                }
                if ((lane & 15) == 0) {
                    int gi = b*8 + octile*2 + (lane >> 4);
                    atomicAdd(&g_sum_s[gi], s);
                    atomicAdd(&g_ssq_s[gi], q);
                }
            }
        }
        __syncthreads();
    }
}

// ---------------- launch ----------------
extern "C" void kernel_launch(void* const* d_in, const int* in_sizes, int n_in,
                              void* d_out, int out_size) {
    const float* x0      = (const float*)d_in[0];
    const float* x1      = (const float*)d_in[1];
    const float* g1      = (const float*)d_in[2];
    const float* b1      = (const float*)d_in[3];
    const float* w1c     = (const float*)d_in[4];
    const float* w1k     = (const float*)d_in[5];
    const float* bias1   = (const float*)d_in[6];
    const float* g2      = (const float*)d_in[7];
    const float* b2      = (const float*)d_in[8];
    const float* w2c     = (const float*)d_in[9];
    const float* w2k     = (const float*)d_in[10];
    const float* bias2   = (const float*)d_in[11];
    const float* wskip   = (const float*)d_in[12];
    const float* bskip   = (const float*)d_in[13];
    const float* gskip   = (const float*)d_in[14];
    const float* betask  = (const float*)d_in[15];

    cudaFuncSetAttribute(conv_w_k<1>, cudaFuncAttributeMaxDynamicSharedMemorySize, W_TOTAL);
    cudaFuncSetAttribute(conv_w_k<2>, cudaFuncAttributeMaxDynamicSharedMemorySize, W_TOTAL);

    zero_stats_k<<<1, 128>>>();
    prep_w_k<<<176, 256>>>(w1c, w1k, wskip, w2c, w2k);
    stats_x_k<<<dim3(32, 32), 256>>>(x0, x1);
    finalize1_k<<<1, 32>>>();

    dim3 grid(2, 32, 4);   // z = b + 2*cs
    conv_w_k<1><<<grid, 512, W_TOTAL>>>(x0, x1, bias1, g1, b1,
                                        bskip, nullptr, nullptr, nullptr);
    finalize2_k<<<1, 64>>>();
    conv_w_k<2><<<grid, 512, W_TOTAL>>>(nullptr, nullptr, bias2, g2, b2,
                                        nullptr, gskip, betask, (float*)d_out);
    (void)in_sizes; (void)n_in; (void)out_size;
}